// round 9
// baseline (speedup 1.0000x reference)
#include <cuda_runtime.h>
#include <math.h>
#include <stdint.h>

// Problem constants
#define B_    8
#define C_    320
#define N_    4096     // H*W  (= M of both big GEMMs)
#define SKV_  77
#define DKV_  1024
#define HEADS_ 8
#define DH_   64
#define INNER_ 512
#define MKV_  (B_ * SKV_)   // 616

typedef unsigned long long ull;

// ---- Blackwell packed fp32x2 helpers (bit-exact fp32 per lane) ----
__device__ __forceinline__ void ffma2(ull& d, ull a, ull b) {
    asm("fma.rn.f32x2 %0, %1, %2, %0;" : "+l"(d) : "l"(a), "l"(b));
}
__device__ __forceinline__ ull pack2(float x, float y) {
    ull r; asm("mov.b64 %0, {%1, %2};" : "=l"(r) : "f"(x), "f"(y)); return r;
}
__device__ __forceinline__ float2 unpack2(ull v) {
    float2 r; asm("mov.b64 {%0, %1}, %2;" : "=f"(r.x), "=f"(r.y) : "l"(v)); return r;
}
// ---- cp.async helpers ----
__device__ __forceinline__ void cp_async16(uint32_t smem_addr, const void* gptr) {
    asm volatile("cp.async.ca.shared.global [%0], [%1], 16;\n"
                 :: "r"(smem_addr), "l"(gptr));
}
__device__ __forceinline__ void cp_async_commit() {
    asm volatile("cp.async.commit_group;\n");
}
__device__ __forceinline__ void cp_async_wait_all() {
    asm volatile("cp.async.wait_group 0;\n");
}

// Scratch (allocation-free rule: __device__ globals; referenced ONLY in device code)
__device__ float g_QpT[(size_t)B_ * INNER_ * N_];  // [b][inner][n]
__device__ float g_OT [(size_t)B_ * INNER_ * N_];  // [b][inner][n]
__device__ float g_Kp [(size_t)B_ * SKV_ * INNER_]; // pre-scaled by 1/8
__device__ float g_Vp [(size_t)B_ * SKV_ * INNER_];

// ---------------------------------------------------------------------------
// KV projection: [616,1024] @ [1024,512] -> Kp (scaled) / Vp.  (small GEMM)
// ---------------------------------------------------------------------------
__global__ __launch_bounds__(256) void kv_proj_kernel(
    const float* __restrict__ kv,
    const float* __restrict__ Wk,
    const float* __restrict__ Wv)
{
    const bool isK = (blockIdx.z == 0);
    const float* __restrict__ W = isK ? Wk : Wv;
    float* __restrict__ Cout = isK ? g_Kp : g_Vp;
    const float scale = isK ? 0.125f : 1.0f;

    __shared__ float As[16][64];
    __shared__ float Bs[16][64];

    const int tid = threadIdx.x;
    const int mBase = blockIdx.x * 64;
    const int nBase = blockIdx.y * 64;
    const int rm = tid & 15;
    const int cn = tid >> 4;

    float acc[4][4] = {};

    const int aRow  = tid >> 2;
    const int aCol4 = (tid & 3) * 4;
    const int bRow  = tid >> 4;
    const int bCol4 = (tid & 15) * 4;
    const int gm = mBase + aRow;

    for (int k0 = 0; k0 < DKV_; k0 += 16) {
        float4 av = make_float4(0.f, 0.f, 0.f, 0.f);
        if (gm < MKV_)
            av = *(const float4*)(kv + (size_t)gm * DKV_ + k0 + aCol4);
        As[aCol4 + 0][aRow] = av.x;
        As[aCol4 + 1][aRow] = av.y;
        As[aCol4 + 2][aRow] = av.z;
        As[aCol4 + 3][aRow] = av.w;
        *(float4*)&Bs[bRow][bCol4] =
            *(const float4*)(W + (size_t)(k0 + bRow) * INNER_ + nBase + bCol4);
        __syncthreads();
        #pragma unroll
        for (int kk = 0; kk < 16; ++kk) {
            float a[4], bv[4];
            #pragma unroll
            for (int i = 0; i < 4; ++i) a[i]  = As[kk][rm + 16 * i];
            #pragma unroll
            for (int j = 0; j < 4; ++j) bv[j] = Bs[kk][cn + 16 * j];
            #pragma unroll
            for (int i = 0; i < 4; ++i)
                #pragma unroll
                for (int j = 0; j < 4; ++j)
                    acc[i][j] += a[i] * bv[j];
        }
        __syncthreads();
    }
    #pragma unroll
    for (int i = 0; i < 4; ++i) {
        const int m = mBase + rm + 16 * i;
        if (m < MKV_) {
            #pragma unroll
            for (int j = 0; j < 4; ++j)
                Cout[(size_t)m * INNER_ + nBase + cn + 16 * j] = acc[i][j] * scale;
        }
    }
}

// ---------------------------------------------------------------------------
// Unified big GEMM, MODE-selected scratch (device globals stay device-side):
//   MODE 0 (q_proj):   A = Aarg(query, col-major [K][M]), C = g_QpT
//   MODE 1 (out_proj): A = g_OT,                          C = Carg(out) + bias
// Tile 128(M) x 64(N) x 16(K), 128 threads, 8x8 per thread, FFMA2 microkernel.
// cp.async (LDGSTS) + 2-stage double-buffered smem:
//   - no register staging -> lower regs, 4 CTAs/SM (__launch_bounds__(128,4))
//   - one wait_group + one __syncthreads per K-tile; tile it+1 copies issued
//     after the barrier, landing during compute of tile it.
// Conflict-free smem reads (same byte patterns as R7/R8):
//   A: 8 distinct addrs @16B stride, 4-lane broadcast
//   B: 4 distinct addrs @16B stride, 8-lane broadcast
// ---------------------------------------------------------------------------
template <int MODE>
__global__ __launch_bounds__(128, 4) void gemm_tn_kernel(
    const float* __restrict__ Aarg,
    const float* __restrict__ B,
    const float* __restrict__ bias,
    float* __restrict__ Carg)
{
    constexpr int K    = (MODE == 0) ? C_     : INNER_;
    constexpr int Nout = (MODE == 0) ? INNER_ : C_;

    const int b = blockIdx.z;
    const int mBase = blockIdx.x * 128;
    const int nBase = blockIdx.y * 64;

    const float* __restrict__ A =
        ((MODE == 0) ? Aarg : (const float*)g_OT) + (size_t)b * K * N_;
    float* __restrict__ Cp =
        ((MODE == 0) ? (float*)g_QpT : Carg) + (size_t)b * Nout * N_;

    __shared__ float As[2][16][128];   // 16 KB
    __shared__ float Bs[2][16][64];    //  8 KB

    const int tid  = threadIdx.x;
    const int warp = tid >> 5;
    const int lane = tid & 31;
    const int wm = warp & 1;         // m half: 0 / 64
    const int wn = warp >> 1;        // n half: 0 / 32
    const int lm = lane & 7;
    const int ln = lane >> 3;
    const int mFrag = wm * 64 + lm * 4;     // and +32
    const int nFrag = wn * 32 + ln * 4;     // and +16

    // acc[i][jp]: i = m index (8), jp = n-pair index (4):
    //   jp -> n offsets {0,1},{2,3},{16,17},{18,19} relative to nFrag
    ull acc[8][4];
    #pragma unroll
    for (int i = 0; i < 8; ++i)
        #pragma unroll
        for (int jp = 0; jp < 4; ++jp) acc[i][jp] = 0ull;

    // staging indices: A tile 512 float4 -> 4/thread; B tile 256 float4 -> 2/thread
    const int akc = tid >> 5;
    const int af4 = (tid & 31) * 4;
    const int bkc = tid >> 4;
    const int bf4 = (tid & 15) * 4;

    // precomputed smem byte addresses per stage
    uint32_t sA[2][4], sB[2][2];
    #pragma unroll
    for (int st = 0; st < 2; ++st) {
        #pragma unroll
        for (int r = 0; r < 4; ++r)
            sA[st][r] = (uint32_t)__cvta_generic_to_shared(&As[st][akc + 4 * r][af4]);
        #pragma unroll
        for (int r = 0; r < 2; ++r)
            sB[st][r] = (uint32_t)__cvta_generic_to_shared(&Bs[st][bkc + 8 * r][bf4]);
    }

    constexpr int NT = K / 16;

    // prologue: issue tile 0 -> stage 0
    {
        #pragma unroll
        for (int r = 0; r < 4; ++r)
            cp_async16(sA[0][r], A + (size_t)(akc + 4 * r) * N_ + mBase + af4);
        #pragma unroll
        for (int r = 0; r < 2; ++r)
            cp_async16(sB[0][r], B + (size_t)(bkc + 8 * r) * Nout + nBase + bf4);
        cp_async_commit();
    }

    for (int it = 0; it < NT; ++it) {
        cp_async_wait_all();       // tile it landed (this thread's copies)
        __syncthreads();           // all threads' copies visible; prev compute done

        if (it + 1 < NT) {         // issue tile it+1 into the other stage
            const int k0 = (it + 1) * 16;
            const int st = (it + 1) & 1;
            #pragma unroll
            for (int r = 0; r < 4; ++r)
                cp_async16(sA[st][r], A + (size_t)(k0 + akc + 4 * r) * N_ + mBase + af4);
            #pragma unroll
            for (int r = 0; r < 2; ++r)
                cp_async16(sB[st][r], B + (size_t)(k0 + bkc + 8 * r) * Nout + nBase + bf4);
            cp_async_commit();
        }

        const float (* __restrict__ Asb)[128] = As[it & 1];
        const float (* __restrict__ Bsb)[64]  = Bs[it & 1];

        #pragma unroll
        for (int kk = 0; kk < 16; ++kk) {
            const float4 a0 = *(const float4*)&Asb[kk][mFrag];
            const float4 a1 = *(const float4*)&Asb[kk][mFrag + 32];
            const ulonglong2 b0 = *(const ulonglong2*)&Bsb[kk][nFrag];
            const ulonglong2 b1 = *(const ulonglong2*)&Bsb[kk][nFrag + 16];
            const ull bp[4] = { b0.x, b0.y, b1.x, b1.y };
            ull ad[8];
            ad[0] = pack2(a0.x, a0.x); ad[1] = pack2(a0.y, a0.y);
            ad[2] = pack2(a0.z, a0.z); ad[3] = pack2(a0.w, a0.w);
            ad[4] = pack2(a1.x, a1.x); ad[5] = pack2(a1.y, a1.y);
            ad[6] = pack2(a1.z, a1.z); ad[7] = pack2(a1.w, a1.w);
            #pragma unroll
            for (int i = 0; i < 8; ++i)
                #pragma unroll
                for (int jp = 0; jp < 4; ++jp)
                    ffma2(acc[i][jp], ad[i], bp[jp]);
        }
    }

    // epilogue: C[n][m], float4 along m (coalesced)
    #pragma unroll
    for (int jp = 0; jp < 4; ++jp) {
        const int nOff = ((jp & 1) * 2) + ((jp >> 1) * 16);
        float2 v[8];
        #pragma unroll
        for (int i = 0; i < 8; ++i) v[i] = unpack2(acc[i][jp]);

        {   // lo half of pair: n = nBase + nFrag + nOff
            const int n = nBase + nFrag + nOff;
            const float bb = (MODE == 1) ? bias[n] : 0.f;
            float* p = Cp + (size_t)n * N_ + mBase;
            *(float4*)(p + mFrag) =
                make_float4(v[0].x + bb, v[1].x + bb, v[2].x + bb, v[3].x + bb);
            *(float4*)(p + mFrag + 32) =
                make_float4(v[4].x + bb, v[5].x + bb, v[6].x + bb, v[7].x + bb);
        }
        {   // hi half: n + 1
            const int n = nBase + nFrag + nOff + 1;
            const float bb = (MODE == 1) ? bias[n] : 0.f;
            float* p = Cp + (size_t)n * N_ + mBase;
            *(float4*)(p + mFrag) =
                make_float4(v[0].y + bb, v[1].y + bb, v[2].y + bb, v[3].y + bb);
            *(float4*)(p + mFrag + 32) =
                make_float4(v[4].y + bb, v[5].y + bb, v[6].y + bb, v[7].y + bb);
        }
    }
}

// ---------------------------------------------------------------------------
// Attention: one thread per query row; FFMA2 in QK^T and AV phases.
// All smem KV reads are warp-broadcast (same address) -> conflict-free.
// ---------------------------------------------------------------------------
#define ATTN_SMEM_BYTES ((SKV_ * DH_ + SKV_ * 128) * (int)sizeof(float))  // 59136

__global__ __launch_bounds__(128) void attn_kernel()
{
    extern __shared__ float sm[];
    float* __restrict__ KV = sm;                 // 77*64
    float* __restrict__ L  = sm + SKV_ * DH_;    // [77][128]

    const int b = blockIdx.z;
    const int h = blockIdx.y;
    const int tid = threadIdx.x;
    const int n = blockIdx.x * 128 + tid;

    // q row -> packed pairs (coalesced gmem reads across n)
    ull q2[DH_ / 2];
    {
        const float* __restrict__ qp =
            g_QpT + (size_t)b * INNER_ * N_ + (size_t)h * DH_ * N_ + n;
        #pragma unroll
        for (int p = 0; p < DH_ / 2; ++p)
            q2[p] = pack2(qp[(size_t)(2 * p) * N_], qp[(size_t)(2 * p + 1) * N_]);
    }

    // stage K (pre-scaled)
    {
        const float* __restrict__ kp = g_Kp + (size_t)b * SKV_ * INNER_ + h * DH_;
        for (int i4 = tid; i4 < SKV_ * DH_ / 4; i4 += 128) {
            const int s = i4 >> 4, d4 = (i4 & 15) << 2;
            *(float4*)(KV + (i4 << 2)) = *(const float4*)(kp + (size_t)s * INNER_ + d4);
        }
    }
    __syncthreads();

    // logits + max
    float maxv = -1e30f;
    for (int s = 0; s < SKV_; ++s) {
        ull da = 0ull, db = 0ull;   // two chains to break RAW latency
        #pragma unroll
        for (int j = 0; j < 16; j += 2) {
            const ulonglong2 k0 = *(const ulonglong2*)(KV + s * DH_ + j * 4);
            const ulonglong2 k1 = *(const ulonglong2*)(KV + s * DH_ + j * 4 + 4);
            ffma2(da, q2[2 * j],     k0.x);
            ffma2(da, q2[2 * j + 1], k0.y);
            ffma2(db, q2[2 * j + 2], k1.x);
            ffma2(db, q2[2 * j + 3], k1.y);
        }
        const float2 pa = unpack2(da), pb = unpack2(db);
        const float dot = (pa.x + pa.y) + (pb.x + pb.y);
        L[s * 128 + tid] = dot;
        maxv = fmaxf(maxv, dot);
    }

    // softmax numerator + sum
    float sum = 0.f;
    for (int s = 0; s < SKV_; ++s) {
        const float e = __expf(L[s * 128 + tid] - maxv);
        L[s * 128 + tid] = e;
        sum += e;
    }
    const float inv = 1.f / sum;

    __syncthreads();  // all K reads done before V overwrites buffer

    // stage V
    {
        const float* __restrict__ vp = g_Vp + (size_t)b * SKV_ * INNER_ + h * DH_;
        for (int i4 = tid; i4 < SKV_ * DH_ / 4; i4 += 128) {
            const int s = i4 >> 4, d4 = (i4 & 15) << 2;
            *(float4*)(KV + (i4 << 2)) = *(const float4*)(vp + (size_t)s * INNER_ + d4);
        }
    }
    __syncthreads();

    // AV
    ull acc2[DH_ / 2];
    #pragma unroll
    for (int p = 0; p < DH_ / 2; ++p) acc2[p] = 0ull;
    for (int s = 0; s < SKV_; ++s) {
        const float p = L[s * 128 + tid];
        const ull p2 = pack2(p, p);
        #pragma unroll
        for (int j = 0; j < 16; ++j) {
            const ulonglong2 v2 = *(const ulonglong2*)(KV + s * DH_ + j * 4);
            ffma2(acc2[2 * j],     p2, v2.x);
            ffma2(acc2[2 * j + 1], p2, v2.y);
        }
    }

    // store O transposed (coalesced)
    float* __restrict__ op =
        g_OT + (size_t)b * INNER_ * N_ + (size_t)h * DH_ * N_ + n;
    #pragma unroll
    for (int p = 0; p < DH_ / 2; ++p) {
        const float2 v = unpack2(acc2[p]);
        op[(size_t)(2 * p) * N_]     = v.x * inv;
        op[(size_t)(2 * p + 1) * N_] = v.y * inv;
    }
}

// ---------------------------------------------------------------------------
extern "C" void kernel_launch(void* const* d_in, const int* in_sizes, int n_in,
                              void* d_out, int out_size)
{
    const float* query = (const float*)d_in[0];  // [B,C,H,W]
    const float* kv    = (const float*)d_in[1];  // [B,S,DKV]
    const float* Wq    = (const float*)d_in[2];  // [C,INNER]
    const float* Wk    = (const float*)d_in[3];  // [DKV,INNER]
    const float* Wv    = (const float*)d_in[4];  // [DKV,INNER]
    const float* Wo    = (const float*)d_in[5];  // [INNER,C]
    const float* bo    = (const float*)d_in[6];  // [C]
    float* out = (float*)d_out;

    cudaFuncSetAttribute(attn_kernel,
                         cudaFuncAttributeMaxDynamicSharedMemorySize,
                         ATTN_SMEM_BYTES);

    {   // K & V projections
        dim3 grid((MKV_ + 63) / 64, INNER_ / 64, 2);   // 10 x 8 x 2
        kv_proj_kernel<<<grid, 256>>>(kv, Wk, Wv);
    }
    {   // Q projection: A=query (col-major), C -> g_QpT (selected in-kernel)
        dim3 grid(N_ / 128, INNER_ / 64, B_);          // 32 x 8 x 8
        gemm_tn_kernel<0><<<grid, 128>>>(query, Wq, nullptr, nullptr);
    }
    {   // attention
        dim3 grid(N_ / 128, HEADS_, B_);               // 32 x 8 x 8
        attn_kernel<<<grid, 128, ATTN_SMEM_BYTES>>>();
    }
    {   // output projection: A = g_OT (in-kernel), C = out (NCHW) + bias
        dim3 grid(N_ / 128, C_ / 64, B_);              // 32 x 5 x 8
        gemm_tn_kernel<1><<<grid, 128>>>(nullptr, Wo, bo, out);
    }
}

// round 10
// speedup vs baseline: 1.0340x; 1.0340x over previous
#include <cuda_runtime.h>
#include <math.h>
#include <stdint.h>

// Problem constants
#define B_    8
#define C_    320
#define N_    4096     // H*W  (= M of both big GEMMs)
#define SKV_  77
#define DKV_  1024
#define HEADS_ 8
#define DH_   64
#define INNER_ 512
#define MKV_  (B_ * SKV_)   // 616

typedef unsigned long long ull;

// ---- Blackwell packed fp32x2 helpers (bit-exact fp32 per lane) ----
__device__ __forceinline__ void ffma2(ull& d, ull a, ull b) {
    asm("fma.rn.f32x2 %0, %1, %2, %0;" : "+l"(d) : "l"(a), "l"(b));
}
__device__ __forceinline__ void mul2(ull& d, ull a) {
    asm("mul.rn.f32x2 %0, %0, %1;" : "+l"(d) : "l"(a));
}
__device__ __forceinline__ ull pack2(float x, float y) {
    ull r; asm("mov.b64 %0, {%1, %2};" : "=l"(r) : "f"(x), "f"(y)); return r;
}
__device__ __forceinline__ float2 unpack2(ull v) {
    float2 r; asm("mov.b64 {%0, %1}, %2;" : "=f"(r.x), "=f"(r.y) : "l"(v)); return r;
}

// Scratch (allocation-free rule: __device__ globals; referenced ONLY in device code)
__device__ float g_QpT[(size_t)B_ * INNER_ * N_];  // [b][inner][n]
__device__ float g_OT [(size_t)B_ * INNER_ * N_];  // [b][inner][n]
__device__ float g_Kp [(size_t)B_ * SKV_ * INNER_]; // pre-scaled by 1/8
__device__ float g_Vp [(size_t)B_ * SKV_ * INNER_];

// ---------------------------------------------------------------------------
// KV projection: [616,1024] @ [1024,512] -> Kp (scaled) / Vp.  (small GEMM)
// ---------------------------------------------------------------------------
__global__ __launch_bounds__(256) void kv_proj_kernel(
    const float* __restrict__ kv,
    const float* __restrict__ Wk,
    const float* __restrict__ Wv)
{
    const bool isK = (blockIdx.z == 0);
    const float* __restrict__ W = isK ? Wk : Wv;
    float* __restrict__ Cout = isK ? g_Kp : g_Vp;
    const float scale = isK ? 0.125f : 1.0f;

    __shared__ float As[16][64];
    __shared__ float Bs[16][64];

    const int tid = threadIdx.x;
    const int mBase = blockIdx.x * 64;
    const int nBase = blockIdx.y * 64;
    const int rm = tid & 15;
    const int cn = tid >> 4;

    float acc[4][4] = {};

    const int aRow  = tid >> 2;
    const int aCol4 = (tid & 3) * 4;
    const int bRow  = tid >> 4;
    const int bCol4 = (tid & 15) * 4;
    const int gm = mBase + aRow;

    for (int k0 = 0; k0 < DKV_; k0 += 16) {
        float4 av = make_float4(0.f, 0.f, 0.f, 0.f);
        if (gm < MKV_)
            av = *(const float4*)(kv + (size_t)gm * DKV_ + k0 + aCol4);
        As[aCol4 + 0][aRow] = av.x;
        As[aCol4 + 1][aRow] = av.y;
        As[aCol4 + 2][aRow] = av.z;
        As[aCol4 + 3][aRow] = av.w;
        *(float4*)&Bs[bRow][bCol4] =
            *(const float4*)(W + (size_t)(k0 + bRow) * INNER_ + nBase + bCol4);
        __syncthreads();
        #pragma unroll
        for (int kk = 0; kk < 16; ++kk) {
            float a[4], bv[4];
            #pragma unroll
            for (int i = 0; i < 4; ++i) a[i]  = As[kk][rm + 16 * i];
            #pragma unroll
            for (int j = 0; j < 4; ++j) bv[j] = Bs[kk][cn + 16 * j];
            #pragma unroll
            for (int i = 0; i < 4; ++i)
                #pragma unroll
                for (int j = 0; j < 4; ++j)
                    acc[i][j] += a[i] * bv[j];
        }
        __syncthreads();
    }
    #pragma unroll
    for (int i = 0; i < 4; ++i) {
        const int m = mBase + rm + 16 * i;
        if (m < MKV_) {
            #pragma unroll
            for (int j = 0; j < 4; ++j)
                Cout[(size_t)m * INNER_ + nBase + cn + 16 * j] = acc[i][j] * scale;
        }
    }
}

// ---------------------------------------------------------------------------
// Unified big GEMM (R8 register-prefetch variant — best measured):
//   MODE 0 (q_proj):   A = Aarg(query, col-major [K][M]), C = g_QpT
//   MODE 1 (out_proj): A = g_OT,                          C = Carg(out) + bias
// Tile 128(M) x 64(N) x 16(K), 128 threads, 8x8 per thread, FFMA2 microkernel.
// ---------------------------------------------------------------------------
template <int MODE>
__global__ __launch_bounds__(128) void gemm_tn_kernel(
    const float* __restrict__ Aarg,
    const float* __restrict__ B,
    const float* __restrict__ bias,
    float* __restrict__ Carg)
{
    constexpr int K    = (MODE == 0) ? C_     : INNER_;
    constexpr int Nout = (MODE == 0) ? INNER_ : C_;

    const int b = blockIdx.z;
    const int mBase = blockIdx.x * 128;
    const int nBase = blockIdx.y * 64;

    const float* __restrict__ A =
        ((MODE == 0) ? Aarg : (const float*)g_OT) + (size_t)b * K * N_;
    float* __restrict__ Cp =
        ((MODE == 0) ? (float*)g_QpT : Carg) + (size_t)b * Nout * N_;

    __shared__ float As[16][128];
    __shared__ float Bs[16][64];

    const int tid  = threadIdx.x;
    const int warp = tid >> 5;
    const int lane = tid & 31;
    const int wm = warp & 1;
    const int wn = warp >> 1;
    const int lm = lane & 7;
    const int ln = lane >> 3;
    const int mFrag = wm * 64 + lm * 4;     // and +32
    const int nFrag = wn * 32 + ln * 4;     // and +16

    ull acc[8][4];
    #pragma unroll
    for (int i = 0; i < 8; ++i)
        #pragma unroll
        for (int jp = 0; jp < 4; ++jp) acc[i][jp] = 0ull;

    const int akc = tid >> 5;
    const int af4 = (tid & 31) * 4;
    const int bkc = tid >> 4;
    const int bf4 = (tid & 15) * 4;

    float4 aR[4], bR[2];
    constexpr int NT = K / 16;

    #pragma unroll
    for (int r = 0; r < 4; ++r)
        aR[r] = *(const float4*)(A + (size_t)(akc + 4 * r) * N_ + mBase + af4);
    #pragma unroll
    for (int r = 0; r < 2; ++r)
        bR[r] = *(const float4*)(B + (size_t)(bkc + 8 * r) * Nout + nBase + bf4);

    for (int it = 0; it < NT; ++it) {
        #pragma unroll
        for (int r = 0; r < 4; ++r)
            *(float4*)&As[akc + 4 * r][af4] = aR[r];
        #pragma unroll
        for (int r = 0; r < 2; ++r)
            *(float4*)&Bs[bkc + 8 * r][bf4] = bR[r];
        __syncthreads();

        if (it + 1 < NT) {
            const int k0 = (it + 1) * 16;
            #pragma unroll
            for (int r = 0; r < 4; ++r)
                aR[r] = *(const float4*)(A + (size_t)(k0 + akc + 4 * r) * N_ + mBase + af4);
            #pragma unroll
            for (int r = 0; r < 2; ++r)
                bR[r] = *(const float4*)(B + (size_t)(k0 + bkc + 8 * r) * Nout + nBase + bf4);
        }

        #pragma unroll
        for (int kk = 0; kk < 16; ++kk) {
            const float4 a0 = *(const float4*)&As[kk][mFrag];
            const float4 a1 = *(const float4*)&As[kk][mFrag + 32];
            const ulonglong2 b0 = *(const ulonglong2*)&Bs[kk][nFrag];
            const ulonglong2 b1 = *(const ulonglong2*)&Bs[kk][nFrag + 16];
            const ull bp[4] = { b0.x, b0.y, b1.x, b1.y };
            ull ad[8];
            ad[0] = pack2(a0.x, a0.x); ad[1] = pack2(a0.y, a0.y);
            ad[2] = pack2(a0.z, a0.z); ad[3] = pack2(a0.w, a0.w);
            ad[4] = pack2(a1.x, a1.x); ad[5] = pack2(a1.y, a1.y);
            ad[6] = pack2(a1.z, a1.z); ad[7] = pack2(a1.w, a1.w);
            #pragma unroll
            for (int i = 0; i < 8; ++i)
                #pragma unroll
                for (int jp = 0; jp < 4; ++jp)
                    ffma2(acc[i][jp], ad[i], bp[jp]);
        }
        __syncthreads();
    }

    #pragma unroll
    for (int jp = 0; jp < 4; ++jp) {
        const int nOff = ((jp & 1) * 2) + ((jp >> 1) * 16);
        float2 v[8];
        #pragma unroll
        for (int i = 0; i < 8; ++i) v[i] = unpack2(acc[i][jp]);

        {
            const int n = nBase + nFrag + nOff;
            const float bb = (MODE == 1) ? bias[n] : 0.f;
            float* p = Cp + (size_t)n * N_ + mBase;
            *(float4*)(p + mFrag) =
                make_float4(v[0].x + bb, v[1].x + bb, v[2].x + bb, v[3].x + bb);
            *(float4*)(p + mFrag + 32) =
                make_float4(v[4].x + bb, v[5].x + bb, v[6].x + bb, v[7].x + bb);
        }
        {
            const int n = nBase + nFrag + nOff + 1;
            const float bb = (MODE == 1) ? bias[n] : 0.f;
            float* p = Cp + (size_t)n * N_ + mBase;
            *(float4*)(p + mFrag) =
                make_float4(v[0].y + bb, v[1].y + bb, v[2].y + bb, v[3].y + bb);
            *(float4*)(p + mFrag + 32) =
                make_float4(v[4].y + bb, v[5].y + bb, v[6].y + bb, v[7].y + bb);
        }
    }
}

// ---------------------------------------------------------------------------
// Attention, online softmax: one thread per query row, single fused pass over
// S in chunks of 8. K and V both resident in smem (39.4 KB); no logits array.
// All smem reads warp-broadcast -> conflict-free.
// ---------------------------------------------------------------------------
#define ATTN_SMEM_BYTES (2 * SKV_ * DH_ * (int)sizeof(float))  // 39424

template <int CNT>
__device__ __forceinline__ void attn_chunk(
    const float* __restrict__ Ks, const float* __restrict__ Vs, int s0,
    const ull* __restrict__ q2, ull* __restrict__ acc2, float& m, float& sum)
{
    float l[CNT];
    // logits for this chunk
    #pragma unroll
    for (int j = 0; j < CNT; ++j) {
        const int s = s0 + j;
        ull da = 0ull, db = 0ull;
        #pragma unroll
        for (int jj = 0; jj < 16; jj += 2) {
            const ulonglong2 k0 = *(const ulonglong2*)(Ks + s * DH_ + jj * 4);
            const ulonglong2 k1 = *(const ulonglong2*)(Ks + s * DH_ + jj * 4 + 4);
            ffma2(da, q2[2 * jj],     k0.x);
            ffma2(da, q2[2 * jj + 1], k0.y);
            ffma2(db, q2[2 * jj + 2], k1.x);
            ffma2(db, q2[2 * jj + 3], k1.y);
        }
        const float2 pa = unpack2(da), pb = unpack2(db);
        l[j] = (pa.x + pa.y) + (pb.x + pb.y);
    }
    // online max / rescale
    float cmax = l[0];
    #pragma unroll
    for (int j = 1; j < CNT; ++j) cmax = fmaxf(cmax, l[j]);
    const float mn = fmaxf(m, cmax);
    const float corr = __expf(m - mn);
    m = mn;
    sum *= corr;
    const ull c2 = pack2(corr, corr);
    #pragma unroll
    for (int p = 0; p < 32; ++p) mul2(acc2[p], c2);
    #pragma unroll
    for (int j = 0; j < CNT; ++j) { l[j] = __expf(l[j] - mn); sum += l[j]; }
    // AV for this chunk
    #pragma unroll
    for (int j = 0; j < CNT; ++j) {
        const int s = s0 + j;
        const ull p2 = pack2(l[j], l[j]);
        #pragma unroll
        for (int jj = 0; jj < 16; ++jj) {
            const ulonglong2 v2 = *(const ulonglong2*)(Vs + s * DH_ + jj * 4);
            ffma2(acc2[2 * jj],     p2, v2.x);
            ffma2(acc2[2 * jj + 1], p2, v2.y);
        }
    }
}

__global__ __launch_bounds__(128, 3) void attn_kernel()
{
    extern __shared__ float sm[];
    float* __restrict__ Ks = sm;                 // [77][64]
    float* __restrict__ Vs = sm + SKV_ * DH_;    // [77][64]

    const int b = blockIdx.z;
    const int h = blockIdx.y;
    const int tid = threadIdx.x;
    const int n = blockIdx.x * 128 + tid;

    // stage K (pre-scaled) and V together
    {
        const float* __restrict__ kp = g_Kp + (size_t)b * SKV_ * INNER_ + h * DH_;
        const float* __restrict__ vp = g_Vp + (size_t)b * SKV_ * INNER_ + h * DH_;
        for (int i4 = tid; i4 < SKV_ * DH_ / 4; i4 += 128) {
            const int s = i4 >> 4, d4 = (i4 & 15) << 2;
            *(float4*)(Ks + (i4 << 2)) = *(const float4*)(kp + (size_t)s * INNER_ + d4);
            *(float4*)(Vs + (i4 << 2)) = *(const float4*)(vp + (size_t)s * INNER_ + d4);
        }
    }

    // q row -> packed pairs (coalesced gmem reads across n)
    ull q2[DH_ / 2];
    {
        const float* __restrict__ qp =
            g_QpT + (size_t)b * INNER_ * N_ + (size_t)h * DH_ * N_ + n;
        #pragma unroll
        for (int p = 0; p < DH_ / 2; ++p)
            q2[p] = pack2(qp[(size_t)(2 * p) * N_], qp[(size_t)(2 * p + 1) * N_]);
    }
    __syncthreads();

    ull acc2[DH_ / 2];
    #pragma unroll
    for (int p = 0; p < DH_ / 2; ++p) acc2[p] = 0ull;
    float m = -1e30f, sum = 0.f;

    // 77 = 9*8 + 5
    for (int c = 0; c < 9; ++c)
        attn_chunk<8>(Ks, Vs, c * 8, q2, acc2, m, sum);
    attn_chunk<5>(Ks, Vs, 72, q2, acc2, m, sum);

    const float inv = 1.f / sum;

    // store O transposed (coalesced)
    float* __restrict__ op =
        g_OT + (size_t)b * INNER_ * N_ + (size_t)h * DH_ * N_ + n;
    #pragma unroll
    for (int p = 0; p < DH_ / 2; ++p) {
        const float2 v = unpack2(acc2[p]);
        op[(size_t)(2 * p) * N_]     = v.x * inv;
        op[(size_t)(2 * p + 1) * N_] = v.y * inv;
    }
}

// ---------------------------------------------------------------------------
extern "C" void kernel_launch(void* const* d_in, const int* in_sizes, int n_in,
                              void* d_out, int out_size)
{
    const float* query = (const float*)d_in[0];  // [B,C,H,W]
    const float* kv    = (const float*)d_in[1];  // [B,S,DKV]
    const float* Wq    = (const float*)d_in[2];  // [C,INNER]
    const float* Wk    = (const float*)d_in[3];  // [DKV,INNER]
    const float* Wv    = (const float*)d_in[4];  // [DKV,INNER]
    const float* Wo    = (const float*)d_in[5];  // [INNER,C]
    const float* bo    = (const float*)d_in[6];  // [C]
    float* out = (float*)d_out;

    {   // K & V projections
        dim3 grid((MKV_ + 63) / 64, INNER_ / 64, 2);   // 10 x 8 x 2
        kv_proj_kernel<<<grid, 256>>>(kv, Wk, Wv);
    }
    {   // Q projection: A=query (col-major), C -> g_QpT (selected in-kernel)
        dim3 grid(N_ / 128, INNER_ / 64, B_);          // 32 x 8 x 8
        gemm_tn_kernel<0><<<grid, 128>>>(query, Wq, nullptr, nullptr);
    }
    {   // attention (fused online softmax)
        dim3 grid(N_ / 128, HEADS_, B_);               // 32 x 8 x 8
        attn_kernel<<<grid, 128, ATTN_SMEM_BYTES>>>();
    }
    {   // output projection: A = g_OT (in-kernel), C = out (NCHW) + bias
        dim3 grid(N_ / 128, C_ / 64, B_);              // 32 x 5 x 8
        gemm_tn_kernel<1><<<grid, 128>>>(nullptr, Wo, bo, out);
    }
}

// round 13
// speedup vs baseline: 1.3050x; 1.2621x over previous
#include <cuda_runtime.h>
#include <cuda_bf16.h>
#include <math.h>
#include <stdint.h>

// Problem constants
#define B_    8
#define C_    320
#define N_    4096     // H*W  (= M of both big GEMMs)
#define SKV_  77
#define DKV_  1024
#define HEADS_ 8
#define DH_   64
#define INNER_ 512
#define MKV_  (B_ * SKV_)   // 616

typedef unsigned long long ull;

// ---- packed fp32x2 helpers ----
__device__ __forceinline__ void ffma2(ull& d, ull a, ull b) {
    asm("fma.rn.f32x2 %0, %1, %2, %0;" : "+l"(d) : "l"(a), "l"(b));
}
__device__ __forceinline__ void mul2(ull& d, ull a) {
    asm("mul.rn.f32x2 %0, %0, %1;" : "+l"(d) : "l"(a));
}
__device__ __forceinline__ ull pack2(float x, float y) {
    ull r; asm("mov.b64 %0, {%1, %2};" : "=l"(r) : "f"(x), "f"(y)); return r;
}
__device__ __forceinline__ float2 unpack2(ull v) {
    float2 r; asm("mov.b64 {%0, %1}, %2;" : "=f"(r.x), "=f"(r.y) : "l"(v)); return r;
}

// ---- portable tensor-core primitives (sm_80+; legal on compute_103) ----
__device__ __forceinline__ uint32_t smem_u32(const void* p) {
    uint32_t a;
    asm("{ .reg .u64 t; cvta.to.shared.u64 t, %1; cvt.u32.u64 %0, t; }"
        : "=r"(a) : "l"(p));
    return a;
}
__device__ __forceinline__ void ldm_x4(uint32_t* r, uint32_t addr) {
    asm volatile("ldmatrix.sync.aligned.m8n8.x4.shared.b16 {%0,%1,%2,%3}, [%4];"
        : "=r"(r[0]), "=r"(r[1]), "=r"(r[2]), "=r"(r[3]) : "r"(addr));
}
__device__ __forceinline__ void ldm_x2(uint32_t* r, uint32_t addr) {
    asm volatile("ldmatrix.sync.aligned.m8n8.x2.shared.b16 {%0,%1}, [%2];"
        : "=r"(r[0]), "=r"(r[1]) : "r"(addr));
}
__device__ __forceinline__ void mma_bf16(float* d, const uint32_t* a, const uint32_t* b) {
    asm volatile("mma.sync.aligned.m16n8k16.row.col.f32.bf16.bf16.f32 "
        "{%0,%1,%2,%3}, {%4,%5,%6,%7}, {%8,%9}, {%0,%1,%2,%3};"
        : "+f"(d[0]), "+f"(d[1]), "+f"(d[2]), "+f"(d[3])
        : "r"(a[0]), "r"(a[1]), "r"(a[2]), "r"(a[3]), "r"(b[0]), "r"(b[1]));
}
__device__ __forceinline__ void cp_async16(uint32_t smem_addr, const void* gptr) {
    asm volatile("cp.async.ca.shared.global [%0], [%1], 16;\n"
                 :: "r"(smem_addr), "l"(gptr));
}
__device__ __forceinline__ void cp_async_commit() {
    asm volatile("cp.async.commit_group;\n");
}
__device__ __forceinline__ void cp_async_wait_all() {
    asm volatile("cp.async.wait_group 0;\n");
}

// Scratch (__device__ globals; referenced ONLY in device code — R5/R12 lesson)
__device__ float g_QpT[(size_t)B_ * INNER_ * N_];   // [b][inner][n] fp32
__device__ float g_Kp [(size_t)B_ * SKV_ * INNER_]; // pre-scaled
__device__ float g_Vp [(size_t)B_ * SKV_ * INNER_];
__device__ __align__(128) __nv_bfloat16 g_Aqhi[(size_t)B_ * N_ * C_];     // query^T split [b][n][c]
__device__ __align__(128) __nv_bfloat16 g_Aqlo[(size_t)B_ * N_ * C_];
__device__ __align__(128) __nv_bfloat16 g_Ohi [(size_t)B_ * N_ * INNER_]; // attn out split [b][n][inner]
__device__ __align__(128) __nv_bfloat16 g_Olo [(size_t)B_ * N_ * INNER_];
__device__ __align__(128) __nv_bfloat16 g_Bqhi[(size_t)INNER_ * C_];      // Wq^T split [n][k]
__device__ __align__(128) __nv_bfloat16 g_Bqlo[(size_t)INNER_ * C_];
__device__ __align__(128) __nv_bfloat16 g_Bohi[(size_t)C_ * INNER_];      // Wo^T split [n][k]
__device__ __align__(128) __nv_bfloat16 g_Bolo[(size_t)C_ * INNER_];

__device__ __forceinline__ void bfsplit(float x, __nv_bfloat16& h, __nv_bfloat16& l) {
    h = __float2bfloat16(x);
    l = __float2bfloat16(x - __bfloat162float(h));
}

// ---------------------------------------------------------------------------
// Prepass: transpose+split query [C][N] -> [n][c] bf16 hi/lo
// ---------------------------------------------------------------------------
__global__ __launch_bounds__(256) void split_query_kernel(const float* __restrict__ q)
{
    __shared__ float t[32][33];
    const int b = blockIdx.z, nB = blockIdx.x * 32, cB = blockIdx.y * 32;
    const int tx = threadIdx.x, ty = threadIdx.y;
    const float* src = q + (size_t)b * C_ * N_;
    #pragma unroll
    for (int i = 0; i < 4; ++i)
        t[ty + 8 * i][tx] = src[(size_t)(cB + ty + 8 * i) * N_ + nB + tx];
    __syncthreads();
    #pragma unroll
    for (int i = 0; i < 4; ++i) {
        const float x = t[tx][ty + 8 * i];
        __nv_bfloat16 h, l; bfsplit(x, h, l);
        const size_t o = ((size_t)b * N_ + nB + ty + 8 * i) * C_ + cB + tx;
        g_Aqhi[o] = h; g_Aqlo[o] = l;
    }
}

// Prepass: transpose+split weight -> [n][k] bf16 hi/lo.
// WSEL selects src/dst INSIDE device code (device symbols must never be
// evaluated on the host). WSEL 0: Wq [C][INNER] -> g_Bq*; 1: Wo [INNER][C] -> g_Bo*.
template <int WSEL>
__global__ __launch_bounds__(256) void split_w_kernel(const float* __restrict__ src)
{
    constexpr int K    = (WSEL == 0) ? C_     : INNER_;
    constexpr int Nout = (WSEL == 0) ? INNER_ : C_;
    __nv_bfloat16* __restrict__ dhi = (WSEL == 0) ? g_Bqhi : g_Bohi;
    __nv_bfloat16* __restrict__ dlo = (WSEL == 0) ? g_Bqlo : g_Bolo;

    __shared__ float t[32][33];
    const int nB = blockIdx.x * 32, kB = blockIdx.y * 32;
    const int tx = threadIdx.x, ty = threadIdx.y;
    #pragma unroll
    for (int i = 0; i < 4; ++i)
        t[ty + 8 * i][tx] = src[(size_t)(kB + ty + 8 * i) * Nout + nB + tx];
    __syncthreads();
    #pragma unroll
    for (int i = 0; i < 4; ++i) {
        const float x = t[tx][ty + 8 * i];
        __nv_bfloat16 h, l; bfsplit(x, h, l);
        const size_t o = (size_t)(nB + ty + 8 * i) * K + kB + tx;
        dhi[o] = h; dlo[o] = l;
    }
}

// ---------------------------------------------------------------------------
// KV projection (fp32 SIMT, unchanged)
// ---------------------------------------------------------------------------
__global__ __launch_bounds__(256) void kv_proj_kernel(
    const float* __restrict__ kv,
    const float* __restrict__ Wk,
    const float* __restrict__ Wv)
{
    const bool isK = (blockIdx.z == 0);
    const float* __restrict__ W = isK ? Wk : Wv;
    float* __restrict__ Cout = isK ? g_Kp : g_Vp;
    const float scale = isK ? 0.125f : 1.0f;

    __shared__ float As[16][64];
    __shared__ float Bs[16][64];

    const int tid = threadIdx.x;
    const int mBase = blockIdx.x * 64;
    const int nBase = blockIdx.y * 64;
    const int rm = tid & 15;
    const int cn = tid >> 4;
    float acc[4][4] = {};
    const int aRow = tid >> 2, aCol4 = (tid & 3) * 4;
    const int bRow = tid >> 4, bCol4 = (tid & 15) * 4;
    const int gm = mBase + aRow;

    for (int k0 = 0; k0 < DKV_; k0 += 16) {
        float4 av = make_float4(0.f, 0.f, 0.f, 0.f);
        if (gm < MKV_)
            av = *(const float4*)(kv + (size_t)gm * DKV_ + k0 + aCol4);
        As[aCol4 + 0][aRow] = av.x; As[aCol4 + 1][aRow] = av.y;
        As[aCol4 + 2][aRow] = av.z; As[aCol4 + 3][aRow] = av.w;
        *(float4*)&Bs[bRow][bCol4] =
            *(const float4*)(W + (size_t)(k0 + bRow) * INNER_ + nBase + bCol4);
        __syncthreads();
        #pragma unroll
        for (int kk = 0; kk < 16; ++kk) {
            float a[4], bv[4];
            #pragma unroll
            for (int i = 0; i < 4; ++i) a[i] = As[kk][rm + 16 * i];
            #pragma unroll
            for (int j = 0; j < 4; ++j) bv[j] = Bs[kk][cn + 16 * j];
            #pragma unroll
            for (int i = 0; i < 4; ++i)
                #pragma unroll
                for (int j = 0; j < 4; ++j)
                    acc[i][j] += a[i] * bv[j];
        }
        __syncthreads();
    }
    #pragma unroll
    for (int i = 0; i < 4; ++i) {
        const int m = mBase + rm + 16 * i;
        if (m < MKV_)
            #pragma unroll
            for (int j = 0; j < 4; ++j)
                Cout[(size_t)m * INNER_ + nBase + cn + 16 * j] = acc[i][j] * scale;
    }
}

// ---------------------------------------------------------------------------
// mma.sync bf16 2-split GEMM (D += Ahi*Bhi + Ahi*Blo + Alo*Bhi):
//   MODE 0: A = g_Aq* [b][4096][320], B = g_Bq* [512][320], C = g_QpT
//   MODE 1: A = g_O*  [b][4096][512], B = g_Bo* [320][512], C = out + bias
// Block tile M=128, N=64; 4 warps (2x2); warp 64x32 = 4x4 m16n8 tiles.
// K-chunk 32 (two k16 steps). smem rows: 32 bf16 = 64B + 16B pad -> 80B stride.
// cp.async double buffer.
// ---------------------------------------------------------------------------
#define ROWB      80
#define OFF_AHI   0
#define OFF_ALO   (128 * ROWB)                      // 10240
#define OFF_BHI   (2 * 128 * ROWB)                  // 20480
#define OFF_BLO   (2 * 128 * ROWB + 64 * ROWB)      // 25600
#define BUF_BYTES (2 * 128 * ROWB + 2 * 64 * ROWB)  // 30720
#define MMA_SMEM_TOTAL (2 * BUF_BYTES)              // 61440

template <int MODE>
__global__ __launch_bounds__(128) void gemm_mma_kernel(
    const float* __restrict__ bias, float* __restrict__ Carg)
{
    constexpr int K    = (MODE == 0) ? C_     : INNER_;
    constexpr int Nout = (MODE == 0) ? INNER_ : C_;
    constexpr int NT   = K / 32;

    extern __shared__ char dsm[];
    const uint32_t sb = smem_u32(dsm);

    const int b = blockIdx.z;
    const int mBase = blockIdx.x * 128;
    const int nBase = blockIdx.y * 64;
    const int tid  = threadIdx.x;
    const int warp = tid >> 5;
    const int lane = tid & 31;
    const int wm = warp & 1;      // m half 0/64
    const int wn = warp >> 1;     // n half 0/32

    const char* Ahi_g = (const char*)((MODE == 0) ? g_Aqhi : g_Ohi) +
                        ((size_t)b * N_ + mBase) * K * 2;
    const char* Alo_g = (const char*)((MODE == 0) ? g_Aqlo : g_Olo) +
                        ((size_t)b * N_ + mBase) * K * 2;
    const char* Bhi_g = (const char*)((MODE == 0) ? g_Bqhi : g_Bohi) +
                        (size_t)nBase * K * 2;
    const char* Blo_g = (const char*)((MODE == 0) ? g_Bqlo : g_Bolo) +
                        (size_t)nBase * K * 2;

    float acc[4][4][4] = {};

    // staging indices: A 512 16B-chunks (4/thread), B 256 (2/thread)
    const int arow = tid >> 2, ac = (tid & 3) * 16;
    // ldmatrix per-thread offsets
    const uint32_t aoff = (uint32_t)((wm * 64 + (lane & 7) + ((lane >> 3) & 1) * 8) * ROWB
                                     + ((lane >> 4) & 1) * 16);
    const uint32_t boff = (uint32_t)((wn * 32 + (lane & 7)) * ROWB
                                     + ((lane >> 3) & 1) * 16);

    // prologue: stage chunk 0 -> buffer 0
    {
        #pragma unroll
        for (int i = 0; i < 4; ++i) {
            const int r = arow + 32 * i;
            const uint32_t s = sb + (uint32_t)(r * ROWB + ac);
            cp_async16(s + OFF_AHI, Ahi_g + (size_t)r * K * 2 + ac);
            cp_async16(s + OFF_ALO, Alo_g + (size_t)r * K * 2 + ac);
        }
        #pragma unroll
        for (int i = 0; i < 2; ++i) {
            const int r = arow + 32 * i;
            const uint32_t s = sb + (uint32_t)(r * ROWB + ac);
            cp_async16(s + OFF_BHI, Bhi_g + (size_t)r * K * 2 + ac);
            cp_async16(s + OFF_BLO, Blo_g + (size_t)r * K * 2 + ac);
        }
        cp_async_commit();
    }

    for (int t = 0; t < NT; ++t) {
        cp_async_wait_all();
        __syncthreads();

        if (t + 1 < NT) {
            const uint32_t bs = sb + ((t + 1) & 1) * BUF_BYTES;
            const int kB = (t + 1) * 64;   // byte offset into gmem rows
            #pragma unroll
            for (int i = 0; i < 4; ++i) {
                const int r = arow + 32 * i;
                const uint32_t s = bs + (uint32_t)(r * ROWB + ac);
                cp_async16(s + OFF_AHI, Ahi_g + (size_t)r * K * 2 + kB + ac);
                cp_async16(s + OFF_ALO, Alo_g + (size_t)r * K * 2 + kB + ac);
            }
            #pragma unroll
            for (int i = 0; i < 2; ++i) {
                const int r = arow + 32 * i;
                const uint32_t s = bs + (uint32_t)(r * ROWB + ac);
                cp_async16(s + OFF_BHI, Bhi_g + (size_t)r * K * 2 + kB + ac);
                cp_async16(s + OFF_BLO, Blo_g + (size_t)r * K * 2 + kB + ac);
            }
            cp_async_commit();
        }

        const uint32_t cb = sb + (t & 1) * BUF_BYTES;
        #pragma unroll
        for (int ks = 0; ks < 2; ++ks) {
            uint32_t bH[4][2], bL[4][2];
            #pragma unroll
            for (int nt = 0; nt < 4; ++nt) {
                const uint32_t ba = cb + boff + (uint32_t)(nt * 8 * ROWB + ks * 32);
                ldm_x2(bH[nt], ba + OFF_BHI);
                ldm_x2(bL[nt], ba + OFF_BLO);
            }
            #pragma unroll
            for (int mt = 0; mt < 4; ++mt) {
                uint32_t aH[4], aL[4];
                const uint32_t aa = cb + aoff + (uint32_t)(mt * 16 * ROWB + ks * 32);
                ldm_x4(aH, aa + OFF_AHI);
                ldm_x4(aL, aa + OFF_ALO);
                #pragma unroll
                for (int nt = 0; nt < 4; ++nt) {
                    mma_bf16(acc[mt][nt], aH, bH[nt]);
                    mma_bf16(acc[mt][nt], aH, bL[nt]);
                    mma_bf16(acc[mt][nt], aL, bH[nt]);
                }
            }
        }
        __syncthreads();
    }

    // epilogue: C[n][m] (+bias). Fragment: d0,d1 @ row r, cols c,c+1; d2,d3 @ r+8.
    float* __restrict__ Cp =
        ((MODE == 0) ? (float*)g_QpT : Carg) + (size_t)b * Nout * N_;
    const int mW = mBase + wm * 64 + (lane >> 2);
    const int nW = nBase + wn * 32 + (lane & 3) * 2;
    #pragma unroll
    for (int mt = 0; mt < 4; ++mt) {
        const int m0 = mW + mt * 16;
        #pragma unroll
        for (int nt = 0; nt < 4; ++nt) {
            const int nn = nW + nt * 8;
            const float b0 = (MODE == 1) ? bias[nn] : 0.f;
            const float b1 = (MODE == 1) ? bias[nn + 1] : 0.f;
            float* p0 = Cp + (size_t)nn * N_;
            float* p1 = Cp + (size_t)(nn + 1) * N_;
            p0[m0]     = acc[mt][nt][0] + b0;
            p1[m0]     = acc[mt][nt][1] + b1;
            p0[m0 + 8] = acc[mt][nt][2] + b0;
            p1[m0 + 8] = acc[mt][nt][3] + b1;
        }
    }
}

// ---------------------------------------------------------------------------
// Attention (fused online softmax), O written as bf16 hi/lo [b][n][inner]
// ---------------------------------------------------------------------------
#define ATTN_SMEM_BYTES (2 * SKV_ * DH_ * (int)sizeof(float))  // 39424

template <int CNT>
__device__ __forceinline__ void attn_chunk(
    const float* __restrict__ Ks, const float* __restrict__ Vs, int s0,
    const ull* __restrict__ q2, ull* __restrict__ acc2, float& m, float& sum)
{
    float l[CNT];
    #pragma unroll
    for (int j = 0; j < CNT; ++j) {
        const int s = s0 + j;
        ull da = 0ull, db = 0ull;
        #pragma unroll
        for (int jj = 0; jj < 16; jj += 2) {
            const ulonglong2 k0 = *(const ulonglong2*)(Ks + s * DH_ + jj * 4);
            const ulonglong2 k1 = *(const ulonglong2*)(Ks + s * DH_ + jj * 4 + 4);
            ffma2(da, q2[2 * jj],     k0.x);
            ffma2(da, q2[2 * jj + 1], k0.y);
            ffma2(db, q2[2 * jj + 2], k1.x);
            ffma2(db, q2[2 * jj + 3], k1.y);
        }
        const float2 pa = unpack2(da), pb = unpack2(db);
        l[j] = (pa.x + pa.y) + (pb.x + pb.y);
    }
    float cmax = l[0];
    #pragma unroll
    for (int j = 1; j < CNT; ++j) cmax = fmaxf(cmax, l[j]);
    const float mn = fmaxf(m, cmax);
    const float corr = __expf(m - mn);
    m = mn;
    sum *= corr;
    const ull c2 = pack2(corr, corr);
    #pragma unroll
    for (int p = 0; p < 32; ++p) mul2(acc2[p], c2);
    #pragma unroll
    for (int j = 0; j < CNT; ++j) { l[j] = __expf(l[j] - mn); sum += l[j]; }
    #pragma unroll
    for (int j = 0; j < CNT; ++j) {
        const int s = s0 + j;
        const ull p2 = pack2(l[j], l[j]);
        #pragma unroll
        for (int jj = 0; jj < 16; ++jj) {
            const ulonglong2 v2 = *(const ulonglong2*)(Vs + s * DH_ + jj * 4);
            ffma2(acc2[2 * jj],     p2, v2.x);
            ffma2(acc2[2 * jj + 1], p2, v2.y);
        }
    }
}

__global__ __launch_bounds__(128, 3) void attn_kernel()
{
    extern __shared__ float sm[];
    float* __restrict__ Ks = sm;
    float* __restrict__ Vs = sm + SKV_ * DH_;

    const int b = blockIdx.z;
    const int h = blockIdx.y;
    const int tid = threadIdx.x;
    const int n = blockIdx.x * 128 + tid;

    {
        const float* __restrict__ kp = g_Kp + (size_t)b * SKV_ * INNER_ + h * DH_;
        const float* __restrict__ vp = g_Vp + (size_t)b * SKV_ * INNER_ + h * DH_;
        for (int i4 = tid; i4 < SKV_ * DH_ / 4; i4 += 128) {
            const int s = i4 >> 4, d4 = (i4 & 15) << 2;
            *(float4*)(Ks + (i4 << 2)) = *(const float4*)(kp + (size_t)s * INNER_ + d4);
            *(float4*)(Vs + (i4 << 2)) = *(const float4*)(vp + (size_t)s * INNER_ + d4);
        }
    }

    ull q2[DH_ / 2];
    {
        const float* __restrict__ qp =
            g_QpT + (size_t)b * INNER_ * N_ + (size_t)h * DH_ * N_ + n;
        #pragma unroll
        for (int p = 0; p < DH_ / 2; ++p)
            q2[p] = pack2(qp[(size_t)(2 * p) * N_], qp[(size_t)(2 * p + 1) * N_]);
    }
    __syncthreads();

    ull acc2[DH_ / 2];
    #pragma unroll
    for (int p = 0; p < DH_ / 2; ++p) acc2[p] = 0ull;
    float m = -1e30f, sum = 0.f;

    for (int c = 0; c < 9; ++c)
        attn_chunk<8>(Ks, Vs, c * 8, q2, acc2, m, sum);
    attn_chunk<5>(Ks, Vs, 72, q2, acc2, m, sum);

    const float inv = 1.f / sum;

    alignas(16) __nv_bfloat16 hib[DH_], lob[DH_];
    #pragma unroll
    for (int p = 0; p < DH_ / 2; ++p) {
        const float2 v = unpack2(acc2[p]);
        bfsplit(v.x * inv, hib[2 * p], lob[2 * p]);
        bfsplit(v.y * inv, hib[2 * p + 1], lob[2 * p + 1]);
    }
    const size_t off = ((size_t)b * N_ + n) * INNER_ + h * DH_;
    char* hp = (char*)g_Ohi + off * 2;
    char* lp = (char*)g_Olo + off * 2;
    #pragma unroll
    for (int i = 0; i < 8; ++i) {
        *(uint4*)(hp + 16 * i) = ((const uint4*)hib)[i];
        *(uint4*)(lp + 16 * i) = ((const uint4*)lob)[i];
    }
}

// ---------------------------------------------------------------------------
extern "C" void kernel_launch(void* const* d_in, const int* in_sizes, int n_in,
                              void* d_out, int out_size)
{
    const float* query = (const float*)d_in[0];  // [B,C,H,W]
    const float* kv    = (const float*)d_in[1];  // [B,S,DKV]
    const float* Wq    = (const float*)d_in[2];  // [C,INNER]
    const float* Wk    = (const float*)d_in[3];  // [DKV,INNER]
    const float* Wv    = (const float*)d_in[4];  // [DKV,INNER]
    const float* Wo    = (const float*)d_in[5];  // [INNER,C]
    const float* bo    = (const float*)d_in[6];  // [C]
    float* out = (float*)d_out;

    cudaFuncSetAttribute(gemm_mma_kernel<0>,
                         cudaFuncAttributeMaxDynamicSharedMemorySize, MMA_SMEM_TOTAL);
    cudaFuncSetAttribute(gemm_mma_kernel<1>,
                         cudaFuncAttributeMaxDynamicSharedMemorySize, MMA_SMEM_TOTAL);

    {   // prepass: transpose+split query and weights (dst selected in-kernel)
        dim3 blk(32, 8);
        split_query_kernel<<<dim3(N_ / 32, C_ / 32, B_), blk>>>(query);
        split_w_kernel<0><<<dim3(INNER_ / 32, C_ / 32, 1), blk>>>(Wq);
        split_w_kernel<1><<<dim3(C_ / 32, INNER_ / 32, 1), blk>>>(Wo);
    }
    {   // K & V projections
        dim3 grid((MKV_ + 63) / 64, INNER_ / 64, 2);
        kv_proj_kernel<<<grid, 256>>>(kv, Wk, Wv);
    }
    {   // Q projection (mma.sync bf16 split) -> g_QpT
        dim3 grid(N_ / 128, INNER_ / 64, B_);          // 32 x 8 x 8
        gemm_mma_kernel<0><<<grid, 128, MMA_SMEM_TOTAL>>>(nullptr, nullptr);
    }
    {   // attention (fused online softmax) -> g_Ohi/g_Olo
        dim3 grid(N_ / 128, HEADS_, B_);
        attn_kernel<<<grid, 128, ATTN_SMEM_BYTES>>>();
    }
    {   // output projection (mma.sync bf16 split) -> out (NCHW) + bias
        dim3 grid(N_ / 128, C_ / 64, B_);              // 32 x 5 x 8
        gemm_mma_kernel<1><<<grid, 128, MMA_SMEM_TOTAL>>>(bo, out);
    }
}

// round 14
// speedup vs baseline: 1.3808x; 1.0581x over previous
#include <cuda_runtime.h>
#include <cuda_bf16.h>
#include <math.h>
#include <stdint.h>

// Problem constants
#define B_    8
#define C_    320
#define N_    4096     // H*W  (= M of both big GEMMs)
#define SKV_  77
#define DKV_  1024
#define HEADS_ 8
#define DH_   64
#define INNER_ 512
#define MKV_  (B_ * SKV_)   // 616

typedef unsigned long long ull;

// ---- packed fp32x2 helpers ----
__device__ __forceinline__ void ffma2(ull& d, ull a, ull b) {
    asm("fma.rn.f32x2 %0, %1, %2, %0;" : "+l"(d) : "l"(a), "l"(b));
}
__device__ __forceinline__ void mul2(ull& d, ull a) {
    asm("mul.rn.f32x2 %0, %0, %1;" : "+l"(d) : "l"(a));
}
__device__ __forceinline__ ull pack2(float x, float y) {
    ull r; asm("mov.b64 %0, {%1, %2};" : "=l"(r) : "f"(x), "f"(y)); return r;
}
__device__ __forceinline__ float2 unpack2(ull v) {
    float2 r; asm("mov.b64 {%0, %1}, %2;" : "=f"(r.x), "=f"(r.y) : "l"(v)); return r;
}

// ---- portable tensor-core primitives (sm_80+; legal on compute_103) ----
__device__ __forceinline__ uint32_t smem_u32(const void* p) {
    uint32_t a;
    asm("{ .reg .u64 t; cvta.to.shared.u64 t, %1; cvt.u32.u64 %0, t; }"
        : "=r"(a) : "l"(p));
    return a;
}
__device__ __forceinline__ void ldm_x4(uint32_t* r, uint32_t addr) {
    asm volatile("ldmatrix.sync.aligned.m8n8.x4.shared.b16 {%0,%1,%2,%3}, [%4];"
        : "=r"(r[0]), "=r"(r[1]), "=r"(r[2]), "=r"(r[3]) : "r"(addr));
}
__device__ __forceinline__ void ldm_x2(uint32_t* r, uint32_t addr) {
    asm volatile("ldmatrix.sync.aligned.m8n8.x2.shared.b16 {%0,%1}, [%2];"
        : "=r"(r[0]), "=r"(r[1]) : "r"(addr));
}
__device__ __forceinline__ void mma_bf16(float* d, const uint32_t* a, const uint32_t* b) {
    asm volatile("mma.sync.aligned.m16n8k16.row.col.f32.bf16.bf16.f32 "
        "{%0,%1,%2,%3}, {%4,%5,%6,%7}, {%8,%9}, {%0,%1,%2,%3};"
        : "+f"(d[0]), "+f"(d[1]), "+f"(d[2]), "+f"(d[3])
        : "r"(a[0]), "r"(a[1]), "r"(a[2]), "r"(a[3]), "r"(b[0]), "r"(b[1]));
}
__device__ __forceinline__ void cp_async16(uint32_t smem_addr, const void* gptr) {
    asm volatile("cp.async.ca.shared.global [%0], [%1], 16;\n"
                 :: "r"(smem_addr), "l"(gptr));
}
__device__ __forceinline__ void cp_async_commit() {
    asm volatile("cp.async.commit_group;\n");
}
__device__ __forceinline__ void cp_async_wait_all() {
    asm volatile("cp.async.wait_group 0;\n");
}

// Scratch (__device__ globals; referenced ONLY in device code — R5/R12 lesson)
__device__ float g_QpT[(size_t)B_ * INNER_ * N_];   // [b][inner][n] fp32
__device__ float g_Kp [(size_t)B_ * SKV_ * INNER_]; // pre-scaled
__device__ float g_Vp [(size_t)B_ * SKV_ * INNER_];
__device__ float g_KVpart[8][(size_t)MKV_ * INNER_]; // split-K partials (z = kv*4+ks)
__device__ __align__(128) __nv_bfloat16 g_Aqhi[(size_t)B_ * N_ * C_];     // query^T split [b][n][c]
__device__ __align__(128) __nv_bfloat16 g_Aqlo[(size_t)B_ * N_ * C_];
__device__ __align__(128) __nv_bfloat16 g_Ohi [(size_t)B_ * N_ * INNER_]; // attn out split [b][n][inner]
__device__ __align__(128) __nv_bfloat16 g_Olo [(size_t)B_ * N_ * INNER_];
__device__ __align__(128) __nv_bfloat16 g_Bqhi[(size_t)INNER_ * C_];      // Wq^T split [n][k]
__device__ __align__(128) __nv_bfloat16 g_Bqlo[(size_t)INNER_ * C_];
__device__ __align__(128) __nv_bfloat16 g_Bohi[(size_t)C_ * INNER_];      // Wo^T split [n][k]
__device__ __align__(128) __nv_bfloat16 g_Bolo[(size_t)C_ * INNER_];

__device__ __forceinline__ void bfsplit(float x, __nv_bfloat16& h, __nv_bfloat16& l) {
    h = __float2bfloat16(x);
    l = __float2bfloat16(x - __bfloat162float(h));
}

// ---------------------------------------------------------------------------
// Prepass: transpose+split query [C][N] -> [n][c] bf16 hi/lo
// ---------------------------------------------------------------------------
__global__ __launch_bounds__(256) void split_query_kernel(const float* __restrict__ q)
{
    __shared__ float t[32][33];
    const int b = blockIdx.z, nB = blockIdx.x * 32, cB = blockIdx.y * 32;
    const int tx = threadIdx.x, ty = threadIdx.y;
    const float* src = q + (size_t)b * C_ * N_;
    #pragma unroll
    for (int i = 0; i < 4; ++i)
        t[ty + 8 * i][tx] = src[(size_t)(cB + ty + 8 * i) * N_ + nB + tx];
    __syncthreads();
    #pragma unroll
    for (int i = 0; i < 4; ++i) {
        const float x = t[tx][ty + 8 * i];
        __nv_bfloat16 h, l; bfsplit(x, h, l);
        const size_t o = ((size_t)b * N_ + nB + ty + 8 * i) * C_ + cB + tx;
        g_Aqhi[o] = h; g_Aqlo[o] = l;
    }
}

// Prepass: transpose+split weight -> [n][k] bf16 hi/lo (dst selected in-kernel).
template <int WSEL>
__global__ __launch_bounds__(256) void split_w_kernel(const float* __restrict__ src)
{
    constexpr int K    = (WSEL == 0) ? C_     : INNER_;
    constexpr int Nout = (WSEL == 0) ? INNER_ : C_;
    __nv_bfloat16* __restrict__ dhi = (WSEL == 0) ? g_Bqhi : g_Bohi;
    __nv_bfloat16* __restrict__ dlo = (WSEL == 0) ? g_Bqlo : g_Bolo;

    __shared__ float t[32][33];
    const int nB = blockIdx.x * 32, kB = blockIdx.y * 32;
    const int tx = threadIdx.x, ty = threadIdx.y;
    #pragma unroll
    for (int i = 0; i < 4; ++i)
        t[ty + 8 * i][tx] = src[(size_t)(kB + ty + 8 * i) * Nout + nB + tx];
    __syncthreads();
    #pragma unroll
    for (int i = 0; i < 4; ++i) {
        const float x = t[tx][ty + 8 * i];
        __nv_bfloat16 h, l; bfsplit(x, h, l);
        const size_t o = (size_t)(nB + ty + 8 * i) * K + kB + tx;
        dhi[o] = h; dlo[o] = l;
    }
}

// ---------------------------------------------------------------------------
// KV projection, split-K: z = kv(2) x ks(4). Each CTA: 64x64 tile over K=256.
// 640 CTAs -> ~4.3 CTAs/SM (vs 160 before): latency hidden across CTAs.
// ---------------------------------------------------------------------------
__global__ __launch_bounds__(256) void kv_proj_splitk_kernel(
    const float* __restrict__ kv,
    const float* __restrict__ Wk,
    const float* __restrict__ Wv)
{
    const int z = blockIdx.z;
    const bool isK = (z < 4);
    const int ks = z & 3;
    const float* __restrict__ W = isK ? Wk : Wv;
    float* __restrict__ Cout = g_KVpart[z];

    __shared__ float As[16][64];
    __shared__ float Bs[16][64];

    const int tid = threadIdx.x;
    const int mBase = blockIdx.x * 64;
    const int nBase = blockIdx.y * 64;
    const int rm = tid & 15;
    const int cn = tid >> 4;
    float acc[4][4] = {};
    const int aRow = tid >> 2, aCol4 = (tid & 3) * 4;
    const int bRow = tid >> 4, bCol4 = (tid & 15) * 4;
    const int gm = mBase + aRow;

    const int kLo = ks * 256, kHi = kLo + 256;
    for (int k0 = kLo; k0 < kHi; k0 += 16) {
        float4 av = make_float4(0.f, 0.f, 0.f, 0.f);
        if (gm < MKV_)
            av = *(const float4*)(kv + (size_t)gm * DKV_ + k0 + aCol4);
        As[aCol4 + 0][aRow] = av.x; As[aCol4 + 1][aRow] = av.y;
        As[aCol4 + 2][aRow] = av.z; As[aCol4 + 3][aRow] = av.w;
        *(float4*)&Bs[bRow][bCol4] =
            *(const float4*)(W + (size_t)(k0 + bRow) * INNER_ + nBase + bCol4);
        __syncthreads();
        #pragma unroll
        for (int kk = 0; kk < 16; ++kk) {
            float a[4], bv[4];
            #pragma unroll
            for (int i = 0; i < 4; ++i) a[i] = As[kk][rm + 16 * i];
            #pragma unroll
            for (int j = 0; j < 4; ++j) bv[j] = Bs[kk][cn + 16 * j];
            #pragma unroll
            for (int i = 0; i < 4; ++i)
                #pragma unroll
                for (int j = 0; j < 4; ++j)
                    acc[i][j] += a[i] * bv[j];
        }
        __syncthreads();
    }
    #pragma unroll
    for (int i = 0; i < 4; ++i) {
        const int m = mBase + rm + 16 * i;
        if (m < MKV_)
            #pragma unroll
            for (int j = 0; j < 4; ++j)
                Cout[(size_t)m * INNER_ + nBase + cn + 16 * j] = acc[i][j];
    }
}

// Reduce the 4 split-K partials; apply K scale (0.125). 2464 blocks x 256.
__global__ __launch_bounds__(256) void kv_reduce_kernel()
{
    const size_t PER = (size_t)MKV_ * INNER_;          // 315392
    const size_t idx = (size_t)blockIdx.x * 256 + threadIdx.x;  // < 2*PER
    const int kvsel = (int)(idx / PER);
    const size_t e = idx - (size_t)kvsel * PER;
    const int zb = kvsel * 4;
    const float s = g_KVpart[zb][e] + g_KVpart[zb + 1][e] +
                    g_KVpart[zb + 2][e] + g_KVpart[zb + 3][e];
    if (kvsel == 0) g_Kp[e] = s * 0.125f;
    else            g_Vp[e] = s;
}

// ---------------------------------------------------------------------------
// mma.sync bf16 2-split GEMM (D += Ahi*Bhi + Ahi*Blo + Alo*Bhi):
//   MODE 0: A = g_Aq* [b][4096][320], B = g_Bq* [512][320], C = g_QpT
//   MODE 1: A = g_O*  [b][4096][512], B = g_Bo* [320][512], C = out + bias
// Block tile M=128, N=64; 4 warps (2x2); warp 64x32 = 4x4 m16n8 tiles.
// K-chunk 32. smem rows: 64B + 16B pad -> 80B stride. cp.async double buffer.
// ---------------------------------------------------------------------------
#define ROWB      80
#define OFF_AHI   0
#define OFF_ALO   (128 * ROWB)                      // 10240
#define OFF_BHI   (2 * 128 * ROWB)                  // 20480
#define OFF_BLO   (2 * 128 * ROWB + 64 * ROWB)      // 25600
#define BUF_BYTES (2 * 128 * ROWB + 2 * 64 * ROWB)  // 30720
#define MMA_SMEM_TOTAL (2 * BUF_BYTES)              // 61440

template <int MODE>
__global__ __launch_bounds__(128) void gemm_mma_kernel(
    const float* __restrict__ bias, float* __restrict__ Carg)
{
    constexpr int K    = (MODE == 0) ? C_     : INNER_;
    constexpr int Nout = (MODE == 0) ? INNER_ : C_;
    constexpr int NT   = K / 32;

    extern __shared__ char dsm[];
    const uint32_t sb = smem_u32(dsm);

    const int b = blockIdx.z;
    const int mBase = blockIdx.x * 128;
    const int nBase = blockIdx.y * 64;
    const int tid  = threadIdx.x;
    const int warp = tid >> 5;
    const int lane = tid & 31;
    const int wm = warp & 1;      // m half 0/64
    const int wn = warp >> 1;     // n half 0/32

    const char* Ahi_g = (const char*)((MODE == 0) ? g_Aqhi : g_Ohi) +
                        ((size_t)b * N_ + mBase) * K * 2;
    const char* Alo_g = (const char*)((MODE == 0) ? g_Aqlo : g_Olo) +
                        ((size_t)b * N_ + mBase) * K * 2;
    const char* Bhi_g = (const char*)((MODE == 0) ? g_Bqhi : g_Bohi) +
                        (size_t)nBase * K * 2;
    const char* Blo_g = (const char*)((MODE == 0) ? g_Bqlo : g_Bolo) +
                        (size_t)nBase * K * 2;

    float acc[4][4][4] = {};

    const int arow = tid >> 2, ac = (tid & 3) * 16;
    const uint32_t aoff = (uint32_t)((wm * 64 + (lane & 7) + ((lane >> 3) & 1) * 8) * ROWB
                                     + ((lane >> 4) & 1) * 16);
    const uint32_t boff = (uint32_t)((wn * 32 + (lane & 7)) * ROWB
                                     + ((lane >> 3) & 1) * 16);

    // prologue: stage chunk 0 -> buffer 0
    {
        #pragma unroll
        for (int i = 0; i < 4; ++i) {
            const int r = arow + 32 * i;
            const uint32_t s = sb + (uint32_t)(r * ROWB + ac);
            cp_async16(s + OFF_AHI, Ahi_g + (size_t)r * K * 2 + ac);
            cp_async16(s + OFF_ALO, Alo_g + (size_t)r * K * 2 + ac);
        }
        #pragma unroll
        for (int i = 0; i < 2; ++i) {
            const int r = arow + 32 * i;
            const uint32_t s = sb + (uint32_t)(r * ROWB + ac);
            cp_async16(s + OFF_BHI, Bhi_g + (size_t)r * K * 2 + ac);
            cp_async16(s + OFF_BLO, Blo_g + (size_t)r * K * 2 + ac);
        }
        cp_async_commit();
    }

    for (int t = 0; t < NT; ++t) {
        cp_async_wait_all();
        __syncthreads();

        if (t + 1 < NT) {
            const uint32_t bs = sb + ((t + 1) & 1) * BUF_BYTES;
            const int kB = (t + 1) * 64;
            #pragma unroll
            for (int i = 0; i < 4; ++i) {
                const int r = arow + 32 * i;
                const uint32_t s = bs + (uint32_t)(r * ROWB + ac);
                cp_async16(s + OFF_AHI, Ahi_g + (size_t)r * K * 2 + kB + ac);
                cp_async16(s + OFF_ALO, Alo_g + (size_t)r * K * 2 + kB + ac);
            }
            #pragma unroll
            for (int i = 0; i < 2; ++i) {
                const int r = arow + 32 * i;
                const uint32_t s = bs + (uint32_t)(r * ROWB + ac);
                cp_async16(s + OFF_BHI, Bhi_g + (size_t)r * K * 2 + kB + ac);
                cp_async16(s + OFF_BLO, Blo_g + (size_t)r * K * 2 + kB + ac);
            }
            cp_async_commit();
        }

        const uint32_t cb = sb + (t & 1) * BUF_BYTES;
        #pragma unroll
        for (int ks = 0; ks < 2; ++ks) {
            uint32_t bH[4][2], bL[4][2];
            #pragma unroll
            for (int nt = 0; nt < 4; ++nt) {
                const uint32_t ba = cb + boff + (uint32_t)(nt * 8 * ROWB + ks * 32);
                ldm_x2(bH[nt], ba + OFF_BHI);
                ldm_x2(bL[nt], ba + OFF_BLO);
            }
            #pragma unroll
            for (int mt = 0; mt < 4; ++mt) {
                uint32_t aH[4], aL[4];
                const uint32_t aa = cb + aoff + (uint32_t)(mt * 16 * ROWB + ks * 32);
                ldm_x4(aH, aa + OFF_AHI);
                ldm_x4(aL, aa + OFF_ALO);
                #pragma unroll
                for (int nt = 0; nt < 4; ++nt) {
                    mma_bf16(acc[mt][nt], aH, bH[nt]);
                    mma_bf16(acc[mt][nt], aH, bL[nt]);
                    mma_bf16(acc[mt][nt], aL, bH[nt]);
                }
            }
        }
        __syncthreads();
    }

    // epilogue: C[n][m] (+bias)
    float* __restrict__ Cp =
        ((MODE == 0) ? (float*)g_QpT : Carg) + (size_t)b * Nout * N_;
    const int mW = mBase + wm * 64 + (lane >> 2);
    const int nW = nBase + wn * 32 + (lane & 3) * 2;
    #pragma unroll
    for (int mt = 0; mt < 4; ++mt) {
        const int m0 = mW + mt * 16;
        #pragma unroll
        for (int nt = 0; nt < 4; ++nt) {
            const int nn = nW + nt * 8;
            const float b0 = (MODE == 1) ? bias[nn] : 0.f;
            const float b1 = (MODE == 1) ? bias[nn + 1] : 0.f;
            float* p0 = Cp + (size_t)nn * N_;
            float* p1 = Cp + (size_t)(nn + 1) * N_;
            p0[m0]     = acc[mt][nt][0] + b0;
            p1[m0]     = acc[mt][nt][1] + b1;
            p0[m0 + 8] = acc[mt][nt][2] + b0;
            p1[m0 + 8] = acc[mt][nt][3] + b1;
        }
    }
}

// ---------------------------------------------------------------------------
// Attention (fused online softmax), O written as bf16 hi/lo [b][n][inner]
// ---------------------------------------------------------------------------
#define ATTN_SMEM_BYTES (2 * SKV_ * DH_ * (int)sizeof(float))  // 39424

template <int CNT>
__device__ __forceinline__ void attn_chunk(
    const float* __restrict__ Ks, const float* __restrict__ Vs, int s0,
    const ull* __restrict__ q2, ull* __restrict__ acc2, float& m, float& sum)
{
    float l[CNT];
    #pragma unroll
    for (int j = 0; j < CNT; ++j) {
        const int s = s0 + j;
        ull da = 0ull, db = 0ull;
        #pragma unroll
        for (int jj = 0; jj < 16; jj += 2) {
            const ulonglong2 k0 = *(const ulonglong2*)(Ks + s * DH_ + jj * 4);
            const ulonglong2 k1 = *(const ulonglong2*)(Ks + s * DH_ + jj * 4 + 4);
            ffma2(da, q2[2 * jj],     k0.x);
            ffma2(da, q2[2 * jj + 1], k0.y);
            ffma2(db, q2[2 * jj + 2], k1.x);
            ffma2(db, q2[2 * jj + 3], k1.y);
        }
        const float2 pa = unpack2(da), pb = unpack2(db);
        l[j] = (pa.x + pa.y) + (pb.x + pb.y);
    }
    float cmax = l[0];
    #pragma unroll
    for (int j = 1; j < CNT; ++j) cmax = fmaxf(cmax, l[j]);
    const float mn = fmaxf(m, cmax);
    const float corr = __expf(m - mn);
    m = mn;
    sum *= corr;
    const ull c2 = pack2(corr, corr);
    #pragma unroll
    for (int p = 0; p < 32; ++p) mul2(acc2[p], c2);
    #pragma unroll
    for (int j = 0; j < CNT; ++j) { l[j] = __expf(l[j] - mn); sum += l[j]; }
    #pragma unroll
    for (int j = 0; j < CNT; ++j) {
        const int s = s0 + j;
        const ull p2 = pack2(l[j], l[j]);
        #pragma unroll
        for (int jj = 0; jj < 16; ++jj) {
            const ulonglong2 v2 = *(const ulonglong2*)(Vs + s * DH_ + jj * 4);
            ffma2(acc2[2 * jj],     p2, v2.x);
            ffma2(acc2[2 * jj + 1], p2, v2.y);
        }
    }
}

__global__ __launch_bounds__(128, 3) void attn_kernel()
{
    extern __shared__ float sm[];
    float* __restrict__ Ks = sm;
    float* __restrict__ Vs = sm + SKV_ * DH_;

    const int b = blockIdx.z;
    const int h = blockIdx.y;
    const int tid = threadIdx.x;
    const int n = blockIdx.x * 128 + tid;

    {
        const float* __restrict__ kp = g_Kp + (size_t)b * SKV_ * INNER_ + h * DH_;
        const float* __restrict__ vp = g_Vp + (size_t)b * SKV_ * INNER_ + h * DH_;
        for (int i4 = tid; i4 < SKV_ * DH_ / 4; i4 += 128) {
            const int s = i4 >> 4, d4 = (i4 & 15) << 2;
            *(float4*)(Ks + (i4 << 2)) = *(const float4*)(kp + (size_t)s * INNER_ + d4);
            *(float4*)(Vs + (i4 << 2)) = *(const float4*)(vp + (size_t)s * INNER_ + d4);
        }
    }

    ull q2[DH_ / 2];
    {
        const float* __restrict__ qp =
            g_QpT + (size_t)b * INNER_ * N_ + (size_t)h * DH_ * N_ + n;
        #pragma unroll
        for (int p = 0; p < DH_ / 2; ++p)
            q2[p] = pack2(qp[(size_t)(2 * p) * N_], qp[(size_t)(2 * p + 1) * N_]);
    }
    __syncthreads();

    ull acc2[DH_ / 2];
    #pragma unroll
    for (int p = 0; p < DH_ / 2; ++p) acc2[p] = 0ull;
    float m = -1e30f, sum = 0.f;

    for (int c = 0; c < 9; ++c)
        attn_chunk<8>(Ks, Vs, c * 8, q2, acc2, m, sum);
    attn_chunk<5>(Ks, Vs, 72, q2, acc2, m, sum);

    const float inv = 1.f / sum;

    alignas(16) __nv_bfloat16 hib[DH_], lob[DH_];
    #pragma unroll
    for (int p = 0; p < DH_ / 2; ++p) {
        const float2 v = unpack2(acc2[p]);
        bfsplit(v.x * inv, hib[2 * p], lob[2 * p]);
        bfsplit(v.y * inv, hib[2 * p + 1], lob[2 * p + 1]);
    }
    const size_t off = ((size_t)b * N_ + n) * INNER_ + h * DH_;
    char* hp = (char*)g_Ohi + off * 2;
    char* lp = (char*)g_Olo + off * 2;
    #pragma unroll
    for (int i = 0; i < 8; ++i) {
        *(uint4*)(hp + 16 * i) = ((const uint4*)hib)[i];
        *(uint4*)(lp + 16 * i) = ((const uint4*)lob)[i];
    }
}

// ---------------------------------------------------------------------------
extern "C" void kernel_launch(void* const* d_in, const int* in_sizes, int n_in,
                              void* d_out, int out_size)
{
    const float* query = (const float*)d_in[0];  // [B,C,H,W]
    const float* kv    = (const float*)d_in[1];  // [B,S,DKV]
    const float* Wq    = (const float*)d_in[2];  // [C,INNER]
    const float* Wk    = (const float*)d_in[3];  // [DKV,INNER]
    const float* Wv    = (const float*)d_in[4];  // [DKV,INNER]
    const float* Wo    = (const float*)d_in[5];  // [INNER,C]
    const float* bo    = (const float*)d_in[6];  // [C]
    float* out = (float*)d_out;

    cudaFuncSetAttribute(gemm_mma_kernel<0>,
                         cudaFuncAttributeMaxDynamicSharedMemorySize, MMA_SMEM_TOTAL);
    cudaFuncSetAttribute(gemm_mma_kernel<1>,
                         cudaFuncAttributeMaxDynamicSharedMemorySize, MMA_SMEM_TOTAL);

    {   // prepass: transpose+split query and weights (dst selected in-kernel)
        dim3 blk(32, 8);
        split_query_kernel<<<dim3(N_ / 32, C_ / 32, B_), blk>>>(query);
        split_w_kernel<0><<<dim3(INNER_ / 32, C_ / 32, 1), blk>>>(Wq);
        split_w_kernel<1><<<dim3(C_ / 32, INNER_ / 32, 1), blk>>>(Wo);
    }
    {   // K & V projections: split-K partials then reduce
        dim3 grid((MKV_ + 63) / 64, INNER_ / 64, 8);   // 10 x 8 x 8 = 640 CTAs
        kv_proj_splitk_kernel<<<grid, 256>>>(kv, Wk, Wv);
        kv_reduce_kernel<<<(2 * MKV_ * INNER_) / 256, 256>>>();
    }
    {   // Q projection (mma.sync bf16 split) -> g_QpT
        dim3 grid(N_ / 128, INNER_ / 64, B_);          // 32 x 8 x 8
        gemm_mma_kernel<0><<<grid, 128, MMA_SMEM_TOTAL>>>(nullptr, nullptr);
    }
    {   // attention (fused online softmax) -> g_Ohi/g_Olo
        dim3 grid(N_ / 128, HEADS_, B_);
        attn_kernel<<<grid, 128, ATTN_SMEM_BYTES>>>();
    }
    {   // output projection (mma.sync bf16 split) -> out (NCHW) + bias
        dim3 grid(N_ / 128, C_ / 64, B_);              // 32 x 5 x 8
        gemm_mma_kernel<1><<<grid, 128, MMA_SMEM_TOTAL>>>(bo, out);
    }
}

// round 15
// speedup vs baseline: 1.4380x; 1.0415x over previous
#include <cuda_runtime.h>
#include <cuda_bf16.h>
#include <math.h>
#include <stdint.h>

// Problem constants
#define B_    8
#define C_    320
#define N_    4096     // H*W  (= M of both big GEMMs)
#define SKV_  77
#define DKV_  1024
#define HEADS_ 8
#define DH_   64
#define INNER_ 512
#define MKV_  (B_ * SKV_)   // 616

typedef unsigned long long ull;

// ---- packed fp32x2 helpers ----
__device__ __forceinline__ void ffma2(ull& d, ull a, ull b) {
    asm("fma.rn.f32x2 %0, %1, %2, %0;" : "+l"(d) : "l"(a), "l"(b));
}
__device__ __forceinline__ void mul2(ull& d, ull a) {
    asm("mul.rn.f32x2 %0, %0, %1;" : "+l"(d) : "l"(a));
}
__device__ __forceinline__ ull pack2(float x, float y) {
    ull r; asm("mov.b64 %0, {%1, %2};" : "=l"(r) : "f"(x), "f"(y)); return r;
}
__device__ __forceinline__ float2 unpack2(ull v) {
    float2 r; asm("mov.b64 {%0, %1}, %2;" : "=f"(r.x), "=f"(r.y) : "l"(v)); return r;
}

// ---- portable tensor-core primitives (sm_80+; legal on compute_103) ----
__device__ __forceinline__ uint32_t smem_u32(const void* p) {
    uint32_t a;
    asm("{ .reg .u64 t; cvta.to.shared.u64 t, %1; cvt.u32.u64 %0, t; }"
        : "=r"(a) : "l"(p));
    return a;
}
__device__ __forceinline__ void ldm_x4(uint32_t* r, uint32_t addr) {
    asm volatile("ldmatrix.sync.aligned.m8n8.x4.shared.b16 {%0,%1,%2,%3}, [%4];"
        : "=r"(r[0]), "=r"(r[1]), "=r"(r[2]), "=r"(r[3]) : "r"(addr));
}
__device__ __forceinline__ void ldm_x2(uint32_t* r, uint32_t addr) {
    asm volatile("ldmatrix.sync.aligned.m8n8.x2.shared.b16 {%0,%1}, [%2];"
        : "=r"(r[0]), "=r"(r[1]) : "r"(addr));
}
__device__ __forceinline__ void mma_bf16(float* d, const uint32_t* a, const uint32_t* b) {
    asm volatile("mma.sync.aligned.m16n8k16.row.col.f32.bf16.bf16.f32 "
        "{%0,%1,%2,%3}, {%4,%5,%6,%7}, {%8,%9}, {%0,%1,%2,%3};"
        : "+f"(d[0]), "+f"(d[1]), "+f"(d[2]), "+f"(d[3])
        : "r"(a[0]), "r"(a[1]), "r"(a[2]), "r"(a[3]), "r"(b[0]), "r"(b[1]));
}
__device__ __forceinline__ void cp_async16(uint32_t smem_addr, const void* gptr) {
    asm volatile("cp.async.ca.shared.global [%0], [%1], 16;\n"
                 :: "r"(smem_addr), "l"(gptr));
}
__device__ __forceinline__ void cp_async_commit() {
    asm volatile("cp.async.commit_group;\n");
}
__device__ __forceinline__ void cp_async_wait_all() {
    asm volatile("cp.async.wait_group 0;\n");
}

// Scratch (__device__ globals; referenced ONLY in device code — R5/R12 lesson)
__device__ float g_QpT[(size_t)B_ * INNER_ * N_];   // [b][inner][n] fp32
__device__ float g_Kp [(size_t)B_ * SKV_ * INNER_]; // pre-scaled
__device__ float g_Vp [(size_t)B_ * SKV_ * INNER_];
__device__ float g_KVpart[8][(size_t)MKV_ * INNER_]; // split-K partials (z = kv*4+ks)
__device__ __align__(128) __nv_bfloat16 g_Aqhi[(size_t)B_ * N_ * C_];     // query^T split [b][n][c]
__device__ __align__(128) __nv_bfloat16 g_Aqlo[(size_t)B_ * N_ * C_];
__device__ __align__(128) __nv_bfloat16 g_Ohi [(size_t)B_ * N_ * INNER_]; // attn out split [b][n][inner]
__device__ __align__(128) __nv_bfloat16 g_Olo [(size_t)B_ * N_ * INNER_];
__device__ __align__(128) __nv_bfloat16 g_Bqhi[(size_t)INNER_ * C_];      // Wq^T split [n][k]
__device__ __align__(128) __nv_bfloat16 g_Bqlo[(size_t)INNER_ * C_];
__device__ __align__(128) __nv_bfloat16 g_Bohi[(size_t)C_ * INNER_];      // Wo^T split [n][k]
__device__ __align__(128) __nv_bfloat16 g_Bolo[(size_t)C_ * INNER_];

__device__ __forceinline__ void bfsplit(float x, __nv_bfloat16& h, __nv_bfloat16& l) {
    h = __float2bfloat16(x);
    l = __float2bfloat16(x - __bfloat162float(h));
}

// ---------------------------------------------------------------------------
// Prepass: transpose+split query [C][N] -> [n][c] bf16 hi/lo
// ---------------------------------------------------------------------------
__global__ __launch_bounds__(256) void split_query_kernel(const float* __restrict__ q)
{
    __shared__ float t[32][33];
    const int b = blockIdx.z, nB = blockIdx.x * 32, cB = blockIdx.y * 32;
    const int tx = threadIdx.x, ty = threadIdx.y;
    const float* src = q + (size_t)b * C_ * N_;
    #pragma unroll
    for (int i = 0; i < 4; ++i)
        t[ty + 8 * i][tx] = src[(size_t)(cB + ty + 8 * i) * N_ + nB + tx];
    __syncthreads();
    #pragma unroll
    for (int i = 0; i < 4; ++i) {
        const float x = t[tx][ty + 8 * i];
        __nv_bfloat16 h, l; bfsplit(x, h, l);
        const size_t o = ((size_t)b * N_ + nB + ty + 8 * i) * C_ + cB + tx;
        g_Aqhi[o] = h; g_Aqlo[o] = l;
    }
}

// Prepass: transpose+split weight -> [n][k] bf16 hi/lo (dst selected in-kernel).
template <int WSEL>
__global__ __launch_bounds__(256) void split_w_kernel(const float* __restrict__ src)
{
    constexpr int K    = (WSEL == 0) ? C_     : INNER_;
    constexpr int Nout = (WSEL == 0) ? INNER_ : C_;
    __nv_bfloat16* __restrict__ dhi = (WSEL == 0) ? g_Bqhi : g_Bohi;
    __nv_bfloat16* __restrict__ dlo = (WSEL == 0) ? g_Bqlo : g_Bolo;

    __shared__ float t[32][33];
    const int nB = blockIdx.x * 32, kB = blockIdx.y * 32;
    const int tx = threadIdx.x, ty = threadIdx.y;
    #pragma unroll
    for (int i = 0; i < 4; ++i)
        t[ty + 8 * i][tx] = src[(size_t)(kB + ty + 8 * i) * Nout + nB + tx];
    __syncthreads();
    #pragma unroll
    for (int i = 0; i < 4; ++i) {
        const float x = t[tx][ty + 8 * i];
        __nv_bfloat16 h, l; bfsplit(x, h, l);
        const size_t o = (size_t)(nB + ty + 8 * i) * K + kB + tx;
        dhi[o] = h; dlo[o] = l;
    }
}

// ---------------------------------------------------------------------------
// KV projection, split-K + FFMA2 8x8 microkernel (R8-proven compute loop).
// z = kv(2) x kseg(4); each CTA: 128x64 tile over K=256. Grid (5, 8, 8).
// A (kv) row-major -> transposed staging (16 scalar STS, banks=tid%32, no
// conflicts). M padded to 640; loads/stores guarded at MKV_=616.
// ---------------------------------------------------------------------------
__global__ __launch_bounds__(128) void kv_proj_splitk_kernel(
    const float* __restrict__ kv,
    const float* __restrict__ Wk,
    const float* __restrict__ Wv)
{
    const int z = blockIdx.z;
    const bool isK = (z < 4);
    const int ksg = z & 3;
    const float* __restrict__ W = isK ? Wk : Wv;
    float* __restrict__ Cout = g_KVpart[z];

    __shared__ float As[16][128];
    __shared__ float Bs[16][64];

    const int tid  = threadIdx.x;
    const int warp = tid >> 5;
    const int lane = tid & 31;
    const int wm = warp & 1;
    const int wn = warp >> 1;
    const int lm = lane & 7;
    const int ln = lane >> 3;
    const int mFrag = wm * 64 + lm * 4;     // and +32
    const int nFrag = wn * 32 + ln * 4;     // and +16

    const int mBase = blockIdx.x * 128;
    const int nBase = blockIdx.y * 64;

    ull acc[8][4];
    #pragma unroll
    for (int i = 0; i < 8; ++i)
        #pragma unroll
        for (int jp = 0; jp < 4; ++jp) acc[i][jp] = 0ull;

    const int gm = mBase + tid;            // A row for staging
    const bool mOK = gm < MKV_;
    const int bkc = tid >> 4, bf4 = (tid & 15) * 4;

    const int kLo = ksg * 256;
    float4 aR[4], bR[2];

    // prologue (chunk 0)
    #pragma unroll
    for (int r = 0; r < 4; ++r)
        aR[r] = mOK ? *(const float4*)(kv + (size_t)gm * DKV_ + kLo + 4 * r)
                    : make_float4(0.f, 0.f, 0.f, 0.f);
    #pragma unroll
    for (int r = 0; r < 2; ++r)
        bR[r] = *(const float4*)(W + (size_t)(kLo + bkc + 8 * r) * INNER_ + nBase + bf4);

    for (int t = 0; t < 16; ++t) {
        // store current chunk (A transposed)
        #pragma unroll
        for (int r = 0; r < 4; ++r) {
            As[4 * r + 0][tid] = aR[r].x;
            As[4 * r + 1][tid] = aR[r].y;
            As[4 * r + 2][tid] = aR[r].z;
            As[4 * r + 3][tid] = aR[r].w;
        }
        #pragma unroll
        for (int r = 0; r < 2; ++r)
            *(float4*)&Bs[bkc + 8 * r][bf4] = bR[r];
        __syncthreads();

        if (t + 1 < 16) {
            const int k0 = kLo + (t + 1) * 16;
            #pragma unroll
            for (int r = 0; r < 4; ++r)
                aR[r] = mOK ? *(const float4*)(kv + (size_t)gm * DKV_ + k0 + 4 * r)
                            : make_float4(0.f, 0.f, 0.f, 0.f);
            #pragma unroll
            for (int r = 0; r < 2; ++r)
                bR[r] = *(const float4*)(W + (size_t)(k0 + bkc + 8 * r) * INNER_ + nBase + bf4);
        }

        #pragma unroll
        for (int kk = 0; kk < 16; ++kk) {
            const float4 a0 = *(const float4*)&As[kk][mFrag];
            const float4 a1 = *(const float4*)&As[kk][mFrag + 32];
            const ulonglong2 b0 = *(const ulonglong2*)&Bs[kk][nFrag];
            const ulonglong2 b1 = *(const ulonglong2*)&Bs[kk][nFrag + 16];
            const ull bp[4] = { b0.x, b0.y, b1.x, b1.y };
            ull ad[8];
            ad[0] = pack2(a0.x, a0.x); ad[1] = pack2(a0.y, a0.y);
            ad[2] = pack2(a0.z, a0.z); ad[3] = pack2(a0.w, a0.w);
            ad[4] = pack2(a1.x, a1.x); ad[5] = pack2(a1.y, a1.y);
            ad[6] = pack2(a1.z, a1.z); ad[7] = pack2(a1.w, a1.w);
            #pragma unroll
            for (int i = 0; i < 8; ++i)
                #pragma unroll
                for (int jp = 0; jp < 4; ++jp)
                    ffma2(acc[i][jp], ad[i], bp[jp]);
        }
        __syncthreads();
    }

    // epilogue: Cout[m][INNER] row-major, float2 per n-pair, m guarded
    #pragma unroll
    for (int i = 0; i < 8; ++i) {
        const int m = mBase + mFrag + ((i < 4) ? i : (i + 28));  // +32 offset half
        if (m < MKV_) {
            float* row = Cout + (size_t)m * INNER_ + nBase + nFrag;
            #pragma unroll
            for (int jp = 0; jp < 4; ++jp) {
                const int off = ((jp & 1) * 2) + ((jp >> 1) * 16);
                const float2 v = unpack2(acc[i][jp]);
                *(float2*)(row + off) = v;
            }
        }
    }
}

// Reduce the 4 split-K partials; apply K scale (0.125). 2464 blocks x 256.
__global__ __launch_bounds__(256) void kv_reduce_kernel()
{
    const size_t PER = (size_t)MKV_ * INNER_;          // 315392
    const size_t idx = (size_t)blockIdx.x * 256 + threadIdx.x;  // < 2*PER
    const int kvsel = (int)(idx / PER);
    const size_t e = idx - (size_t)kvsel * PER;
    const int zb = kvsel * 4;
    const float s = g_KVpart[zb][e] + g_KVpart[zb + 1][e] +
                    g_KVpart[zb + 2][e] + g_KVpart[zb + 3][e];
    if (kvsel == 0) g_Kp[e] = s * 0.125f;
    else            g_Vp[e] = s;
}

// ---------------------------------------------------------------------------
// mma.sync bf16 2-split GEMM (D += Ahi*Bhi + Ahi*Blo + Alo*Bhi):
//   MODE 0: A = g_Aq* [b][4096][320], B = g_Bq* [512][320], C = g_QpT
//   MODE 1: A = g_O*  [b][4096][512], B = g_Bo* [320][512], C = out + bias
// Block tile M=128, N=64; 4 warps (2x2); warp 64x32 = 4x4 m16n8 tiles.
// K-chunk 32. smem rows: 64B + 16B pad -> 80B stride. cp.async double buffer.
// ---------------------------------------------------------------------------
#define ROWB      80
#define OFF_AHI   0
#define OFF_ALO   (128 * ROWB)                      // 10240
#define OFF_BHI   (2 * 128 * ROWB)                  // 20480
#define OFF_BLO   (2 * 128 * ROWB + 64 * ROWB)      // 25600
#define BUF_BYTES (2 * 128 * ROWB + 2 * 64 * ROWB)  // 30720
#define MMA_SMEM_TOTAL (2 * BUF_BYTES)              // 61440

template <int MODE>
__global__ __launch_bounds__(128) void gemm_mma_kernel(
    const float* __restrict__ bias, float* __restrict__ Carg)
{
    constexpr int K    = (MODE == 0) ? C_     : INNER_;
    constexpr int Nout = (MODE == 0) ? INNER_ : C_;
    constexpr int NT   = K / 32;

    extern __shared__ char dsm[];
    const uint32_t sb = smem_u32(dsm);

    const int b = blockIdx.z;
    const int mBase = blockIdx.x * 128;
    const int nBase = blockIdx.y * 64;
    const int tid  = threadIdx.x;
    const int warp = tid >> 5;
    const int lane = tid & 31;
    const int wm = warp & 1;      // m half 0/64
    const int wn = warp >> 1;     // n half 0/32

    const char* Ahi_g = (const char*)((MODE == 0) ? g_Aqhi : g_Ohi) +
                        ((size_t)b * N_ + mBase) * K * 2;
    const char* Alo_g = (const char*)((MODE == 0) ? g_Aqlo : g_Olo) +
                        ((size_t)b * N_ + mBase) * K * 2;
    const char* Bhi_g = (const char*)((MODE == 0) ? g_Bqhi : g_Bohi) +
                        (size_t)nBase * K * 2;
    const char* Blo_g = (const char*)((MODE == 0) ? g_Bqlo : g_Bolo) +
                        (size_t)nBase * K * 2;

    float acc[4][4][4] = {};

    const int arow = tid >> 2, ac = (tid & 3) * 16;
    const uint32_t aoff = (uint32_t)((wm * 64 + (lane & 7) + ((lane >> 3) & 1) * 8) * ROWB
                                     + ((lane >> 4) & 1) * 16);
    const uint32_t boff = (uint32_t)((wn * 32 + (lane & 7)) * ROWB
                                     + ((lane >> 3) & 1) * 16);

    // prologue: stage chunk 0 -> buffer 0
    {
        #pragma unroll
        for (int i = 0; i < 4; ++i) {
            const int r = arow + 32 * i;
            const uint32_t s = sb + (uint32_t)(r * ROWB + ac);
            cp_async16(s + OFF_AHI, Ahi_g + (size_t)r * K * 2 + ac);
            cp_async16(s + OFF_ALO, Alo_g + (size_t)r * K * 2 + ac);
        }
        #pragma unroll
        for (int i = 0; i < 2; ++i) {
            const int r = arow + 32 * i;
            const uint32_t s = sb + (uint32_t)(r * ROWB + ac);
            cp_async16(s + OFF_BHI, Bhi_g + (size_t)r * K * 2 + ac);
            cp_async16(s + OFF_BLO, Blo_g + (size_t)r * K * 2 + ac);
        }
        cp_async_commit();
    }

    for (int t = 0; t < NT; ++t) {
        cp_async_wait_all();
        __syncthreads();

        if (t + 1 < NT) {
            const uint32_t bs = sb + ((t + 1) & 1) * BUF_BYTES;
            const int kB = (t + 1) * 64;
            #pragma unroll
            for (int i = 0; i < 4; ++i) {
                const int r = arow + 32 * i;
                const uint32_t s = bs + (uint32_t)(r * ROWB + ac);
                cp_async16(s + OFF_AHI, Ahi_g + (size_t)r * K * 2 + kB + ac);
                cp_async16(s + OFF_ALO, Alo_g + (size_t)r * K * 2 + kB + ac);
            }
            #pragma unroll
            for (int i = 0; i < 2; ++i) {
                const int r = arow + 32 * i;
                const uint32_t s = bs + (uint32_t)(r * ROWB + ac);
                cp_async16(s + OFF_BHI, Bhi_g + (size_t)r * K * 2 + kB + ac);
                cp_async16(s + OFF_BLO, Blo_g + (size_t)r * K * 2 + kB + ac);
            }
            cp_async_commit();
        }

        const uint32_t cb = sb + (t & 1) * BUF_BYTES;
        #pragma unroll
        for (int ks = 0; ks < 2; ++ks) {
            uint32_t bH[4][2], bL[4][2];
            #pragma unroll
            for (int nt = 0; nt < 4; ++nt) {
                const uint32_t ba = cb + boff + (uint32_t)(nt * 8 * ROWB + ks * 32);
                ldm_x2(bH[nt], ba + OFF_BHI);
                ldm_x2(bL[nt], ba + OFF_BLO);
            }
            #pragma unroll
            for (int mt = 0; mt < 4; ++mt) {
                uint32_t aH[4], aL[4];
                const uint32_t aa = cb + aoff + (uint32_t)(mt * 16 * ROWB + ks * 32);
                ldm_x4(aH, aa + OFF_AHI);
                ldm_x4(aL, aa + OFF_ALO);
                #pragma unroll
                for (int nt = 0; nt < 4; ++nt) {
                    mma_bf16(acc[mt][nt], aH, bH[nt]);
                    mma_bf16(acc[mt][nt], aH, bL[nt]);
                    mma_bf16(acc[mt][nt], aL, bH[nt]);
                }
            }
        }
        __syncthreads();
    }

    // epilogue: C[n][m] (+bias)
    float* __restrict__ Cp =
        ((MODE == 0) ? (float*)g_QpT : Carg) + (size_t)b * Nout * N_;
    const int mW = mBase + wm * 64 + (lane >> 2);
    const int nW = nBase + wn * 32 + (lane & 3) * 2;
    #pragma unroll
    for (int mt = 0; mt < 4; ++mt) {
        const int m0 = mW + mt * 16;
        #pragma unroll
        for (int nt = 0; nt < 4; ++nt) {
            const int nn = nW + nt * 8;
            const float b0 = (MODE == 1) ? bias[nn] : 0.f;
            const float b1 = (MODE == 1) ? bias[nn + 1] : 0.f;
            float* p0 = Cp + (size_t)nn * N_;
            float* p1 = Cp + (size_t)(nn + 1) * N_;
            p0[m0]     = acc[mt][nt][0] + b0;
            p1[m0]     = acc[mt][nt][1] + b1;
            p0[m0 + 8] = acc[mt][nt][2] + b0;
            p1[m0 + 8] = acc[mt][nt][3] + b1;
        }
    }
}

// ---------------------------------------------------------------------------
// Attention (fused online softmax), O written as bf16 hi/lo [b][n][inner]
// ---------------------------------------------------------------------------
#define ATTN_SMEM_BYTES (2 * SKV_ * DH_ * (int)sizeof(float))  // 39424

template <int CNT>
__device__ __forceinline__ void attn_chunk(
    const float* __restrict__ Ks, const float* __restrict__ Vs, int s0,
    const ull* __restrict__ q2, ull* __restrict__ acc2, float& m, float& sum)
{
    float l[CNT];
    #pragma unroll
    for (int j = 0; j < CNT; ++j) {
        const int s = s0 + j;
        ull da = 0ull, db = 0ull;
        #pragma unroll
        for (int jj = 0; jj < 16; jj += 2) {
            const ulonglong2 k0 = *(const ulonglong2*)(Ks + s * DH_ + jj * 4);
            const ulonglong2 k1 = *(const ulonglong2*)(Ks + s * DH_ + jj * 4 + 4);
            ffma2(da, q2[2 * jj],     k0.x);
            ffma2(da, q2[2 * jj + 1], k0.y);
            ffma2(db, q2[2 * jj + 2], k1.x);
            ffma2(db, q2[2 * jj + 3], k1.y);
        }
        const float2 pa = unpack2(da), pb = unpack2(db);
        l[j] = (pa.x + pa.y) + (pb.x + pb.y);
    }
    float cmax = l[0];
    #pragma unroll
    for (int j = 1; j < CNT; ++j) cmax = fmaxf(cmax, l[j]);
    const float mn = fmaxf(m, cmax);
    const float corr = __expf(m - mn);
    m = mn;
    sum *= corr;
    const ull c2 = pack2(corr, corr);
    #pragma unroll
    for (int p = 0; p < 32; ++p) mul2(acc2[p], c2);
    #pragma unroll
    for (int j = 0; j < CNT; ++j) { l[j] = __expf(l[j] - mn); sum += l[j]; }
    #pragma unroll
    for (int j = 0; j < CNT; ++j) {
        const int s = s0 + j;
        const ull p2 = pack2(l[j], l[j]);
        #pragma unroll
        for (int jj = 0; jj < 16; ++jj) {
            const ulonglong2 v2 = *(const ulonglong2*)(Vs + s * DH_ + jj * 4);
            ffma2(acc2[2 * jj],     p2, v2.x);
            ffma2(acc2[2 * jj + 1], p2, v2.y);
        }
    }
}

__global__ __launch_bounds__(128, 3) void attn_kernel()
{
    extern __shared__ float sm[];
    float* __restrict__ Ks = sm;
    float* __restrict__ Vs = sm + SKV_ * DH_;

    const int b = blockIdx.z;
    const int h = blockIdx.y;
    const int tid = threadIdx.x;
    const int n = blockIdx.x * 128 + tid;

    {
        const float* __restrict__ kp = g_Kp + (size_t)b * SKV_ * INNER_ + h * DH_;
        const float* __restrict__ vp = g_Vp + (size_t)b * SKV_ * INNER_ + h * DH_;
        for (int i4 = tid; i4 < SKV_ * DH_ / 4; i4 += 128) {
            const int s = i4 >> 4, d4 = (i4 & 15) << 2;
            *(float4*)(Ks + (i4 << 2)) = *(const float4*)(kp + (size_t)s * INNER_ + d4);
            *(float4*)(Vs + (i4 << 2)) = *(const float4*)(vp + (size_t)s * INNER_ + d4);
        }
    }

    ull q2[DH_ / 2];
    {
        const float* __restrict__ qp =
            g_QpT + (size_t)b * INNER_ * N_ + (size_t)h * DH_ * N_ + n;
        #pragma unroll
        for (int p = 0; p < DH_ / 2; ++p)
            q2[p] = pack2(qp[(size_t)(2 * p) * N_], qp[(size_t)(2 * p + 1) * N_]);
    }
    __syncthreads();

    ull acc2[DH_ / 2];
    #pragma unroll
    for (int p = 0; p < DH_ / 2; ++p) acc2[p] = 0ull;
    float m = -1e30f, sum = 0.f;

    for (int c = 0; c < 9; ++c)
        attn_chunk<8>(Ks, Vs, c * 8, q2, acc2, m, sum);
    attn_chunk<5>(Ks, Vs, 72, q2, acc2, m, sum);

    const float inv = 1.f / sum;

    alignas(16) __nv_bfloat16 hib[DH_], lob[DH_];
    #pragma unroll
    for (int p = 0; p < DH_ / 2; ++p) {
        const float2 v = unpack2(acc2[p]);
        bfsplit(v.x * inv, hib[2 * p], lob[2 * p]);
        bfsplit(v.y * inv, hib[2 * p + 1], lob[2 * p + 1]);
    }
    const size_t off = ((size_t)b * N_ + n) * INNER_ + h * DH_;
    char* hp = (char*)g_Ohi + off * 2;
    char* lp = (char*)g_Olo + off * 2;
    #pragma unroll
    for (int i = 0; i < 8; ++i) {
        *(uint4*)(hp + 16 * i) = ((const uint4*)hib)[i];
        *(uint4*)(lp + 16 * i) = ((const uint4*)lob)[i];
    }
}

// ---------------------------------------------------------------------------
extern "C" void kernel_launch(void* const* d_in, const int* in_sizes, int n_in,
                              void* d_out, int out_size)
{
    const float* query = (const float*)d_in[0];  // [B,C,H,W]
    const float* kv    = (const float*)d_in[1];  // [B,S,DKV]
    const float* Wq    = (const float*)d_in[2];  // [C,INNER]
    const float* Wk    = (const float*)d_in[3];  // [DKV,INNER]
    const float* Wv    = (const float*)d_in[4];  // [DKV,INNER]
    const float* Wo    = (const float*)d_in[5];  // [INNER,C]
    const float* bo    = (const float*)d_in[6];  // [C]
    float* out = (float*)d_out;

    cudaFuncSetAttribute(gemm_mma_kernel<0>,
                         cudaFuncAttributeMaxDynamicSharedMemorySize, MMA_SMEM_TOTAL);
    cudaFuncSetAttribute(gemm_mma_kernel<1>,
                         cudaFuncAttributeMaxDynamicSharedMemorySize, MMA_SMEM_TOTAL);

    {   // prepass: transpose+split query and weights (dst selected in-kernel)
        dim3 blk(32, 8);
        split_query_kernel<<<dim3(N_ / 32, C_ / 32, B_), blk>>>(query);
        split_w_kernel<0><<<dim3(INNER_ / 32, C_ / 32, 1), blk>>>(Wq);
        split_w_kernel<1><<<dim3(C_ / 32, INNER_ / 32, 1), blk>>>(Wo);
    }
    {   // K & V projections: split-K FFMA2 partials then reduce
        dim3 grid(5, INNER_ / 64, 8);   // 5 x 8 x 8 = 320 CTAs (M padded to 640)
        kv_proj_splitk_kernel<<<grid, 128>>>(kv, Wk, Wv);
        kv_reduce_kernel<<<(2 * MKV_ * INNER_) / 256, 256>>>();
    }
    {   // Q projection (mma.sync bf16 split) -> g_QpT
        dim3 grid(N_ / 128, INNER_ / 64, B_);          // 32 x 8 x 8
        gemm_mma_kernel<0><<<grid, 128, MMA_SMEM_TOTAL>>>(nullptr, nullptr);
    }
    {   // attention (fused online softmax) -> g_Ohi/g_Olo
        dim3 grid(N_ / 128, HEADS_, B_);
        attn_kernel<<<grid, 128, ATTN_SMEM_BYTES>>>();
    }
    {   // output projection (mma.sync bf16 split) -> out (NCHW) + bias
        dim3 grid(N_ / 128, C_ / 64, B_);              // 32 x 5 x 8
        gemm_mma_kernel<1><<<grid, 128, MMA_SMEM_TOTAL>>>(bo, out);
    }
}

// round 16
// speedup vs baseline: 1.4409x; 1.0020x over previous
#include <cuda_runtime.h>
#include <cuda_bf16.h>
#include <math.h>
#include <stdint.h>

// Problem constants
#define B_    8
#define C_    320
#define N_    4096     // H*W  (= M of both big GEMMs)
#define SKV_  77
#define DKV_  1024
#define HEADS_ 8
#define DH_   64
#define INNER_ 512
#define MKV_  (B_ * SKV_)   // 616

typedef unsigned long long ull;

// ---- packed fp32x2 helpers ----
__device__ __forceinline__ void ffma2(ull& d, ull a, ull b) {
    asm("fma.rn.f32x2 %0, %1, %2, %0;" : "+l"(d) : "l"(a), "l"(b));
}
__device__ __forceinline__ void mul2(ull& d, ull a) {
    asm("mul.rn.f32x2 %0, %0, %1;" : "+l"(d) : "l"(a));
}
__device__ __forceinline__ ull pack2(float x, float y) {
    ull r; asm("mov.b64 %0, {%1, %2};" : "=l"(r) : "f"(x), "f"(y)); return r;
}
__device__ __forceinline__ float2 unpack2(ull v) {
    float2 r; asm("mov.b64 {%0, %1}, %2;" : "=f"(r.x), "=f"(r.y) : "l"(v)); return r;
}

// ---- portable tensor-core primitives (sm_80+; legal on compute_103) ----
__device__ __forceinline__ uint32_t smem_u32(const void* p) {
    uint32_t a;
    asm("{ .reg .u64 t; cvta.to.shared.u64 t, %1; cvt.u32.u64 %0, t; }"
        : "=r"(a) : "l"(p));
    return a;
}
__device__ __forceinline__ void ldm_x4(uint32_t* r, uint32_t addr) {
    asm volatile("ldmatrix.sync.aligned.m8n8.x4.shared.b16 {%0,%1,%2,%3}, [%4];"
        : "=r"(r[0]), "=r"(r[1]), "=r"(r[2]), "=r"(r[3]) : "r"(addr));
}
__device__ __forceinline__ void ldm_x2(uint32_t* r, uint32_t addr) {
    asm volatile("ldmatrix.sync.aligned.m8n8.x2.shared.b16 {%0,%1}, [%2];"
        : "=r"(r[0]), "=r"(r[1]) : "r"(addr));
}
__device__ __forceinline__ void mma_bf16(float* d, const uint32_t* a, const uint32_t* b) {
    asm volatile("mma.sync.aligned.m16n8k16.row.col.f32.bf16.bf16.f32 "
        "{%0,%1,%2,%3}, {%4,%5,%6,%7}, {%8,%9}, {%0,%1,%2,%3};"
        : "+f"(d[0]), "+f"(d[1]), "+f"(d[2]), "+f"(d[3])
        : "r"(a[0]), "r"(a[1]), "r"(a[2]), "r"(a[3]), "r"(b[0]), "r"(b[1]));
}
__device__ __forceinline__ void cp_async16(uint32_t smem_addr, const void* gptr) {
    asm volatile("cp.async.ca.shared.global [%0], [%1], 16;\n"
                 :: "r"(smem_addr), "l"(gptr));
}
__device__ __forceinline__ void cp_async_commit() {
    asm volatile("cp.async.commit_group;\n");
}
__device__ __forceinline__ void cp_async_wait_all() {
    asm volatile("cp.async.wait_group 0;\n");
}

// Scratch (__device__ globals; referenced ONLY in device code — R5/R12 lesson)
__device__ float g_QpT[(size_t)B_ * INNER_ * N_];   // [b][inner][n] fp32
__device__ float g_Kp [(size_t)B_ * SKV_ * INNER_]; // pre-scaled
__device__ float g_Vp [(size_t)B_ * SKV_ * INNER_];
__device__ float g_KVpart[16][(size_t)MKV_ * INNER_]; // split-K partials (z = kv*8+ks)
__device__ __align__(128) __nv_bfloat16 g_Aqhi[(size_t)B_ * N_ * C_];     // query^T split [b][n][c]
__device__ __align__(128) __nv_bfloat16 g_Aqlo[(size_t)B_ * N_ * C_];
__device__ __align__(128) __nv_bfloat16 g_Ohi [(size_t)B_ * N_ * INNER_]; // attn out split [b][n][inner]
__device__ __align__(128) __nv_bfloat16 g_Olo [(size_t)B_ * N_ * INNER_];
__device__ __align__(128) __nv_bfloat16 g_Bqhi[(size_t)INNER_ * C_];      // Wq^T split [n][k]
__device__ __align__(128) __nv_bfloat16 g_Bqlo[(size_t)INNER_ * C_];
__device__ __align__(128) __nv_bfloat16 g_Bohi[(size_t)C_ * INNER_];      // Wo^T split [n][k]
__device__ __align__(128) __nv_bfloat16 g_Bolo[(size_t)C_ * INNER_];

__device__ __forceinline__ void bfsplit(float x, __nv_bfloat16& h, __nv_bfloat16& l) {
    h = __float2bfloat16(x);
    l = __float2bfloat16(x - __bfloat162float(h));
}

// ---------------------------------------------------------------------------
// Prepass: transpose+split query [C][N] -> [n][c] bf16 hi/lo
// ---------------------------------------------------------------------------
__global__ __launch_bounds__(256) void split_query_kernel(const float* __restrict__ q)
{
    __shared__ float t[32][33];
    const int b = blockIdx.z, nB = blockIdx.x * 32, cB = blockIdx.y * 32;
    const int tx = threadIdx.x, ty = threadIdx.y;
    const float* src = q + (size_t)b * C_ * N_;
    #pragma unroll
    for (int i = 0; i < 4; ++i)
        t[ty + 8 * i][tx] = src[(size_t)(cB + ty + 8 * i) * N_ + nB + tx];
    __syncthreads();
    #pragma unroll
    for (int i = 0; i < 4; ++i) {
        const float x = t[tx][ty + 8 * i];
        __nv_bfloat16 h, l; bfsplit(x, h, l);
        const size_t o = ((size_t)b * N_ + nB + ty + 8 * i) * C_ + cB + tx;
        g_Aqhi[o] = h; g_Aqlo[o] = l;
    }
}

// Prepass: transpose+split weight -> [n][k] bf16 hi/lo (dst selected in-kernel).
template <int WSEL>
__global__ __launch_bounds__(256) void split_w_kernel(const float* __restrict__ src)
{
    constexpr int K    = (WSEL == 0) ? C_     : INNER_;
    constexpr int Nout = (WSEL == 0) ? INNER_ : C_;
    __nv_bfloat16* __restrict__ dhi = (WSEL == 0) ? g_Bqhi : g_Bohi;
    __nv_bfloat16* __restrict__ dlo = (WSEL == 0) ? g_Bqlo : g_Bolo;

    __shared__ float t[32][33];
    const int nB = blockIdx.x * 32, kB = blockIdx.y * 32;
    const int tx = threadIdx.x, ty = threadIdx.y;
    #pragma unroll
    for (int i = 0; i < 4; ++i)
        t[ty + 8 * i][tx] = src[(size_t)(kB + ty + 8 * i) * Nout + nB + tx];
    __syncthreads();
    #pragma unroll
    for (int i = 0; i < 4; ++i) {
        const float x = t[tx][ty + 8 * i];
        __nv_bfloat16 h, l; bfsplit(x, h, l);
        const size_t o = (size_t)(nB + ty + 8 * i) * K + kB + tx;
        dhi[o] = h; dlo[o] = l;
    }
}

// ---------------------------------------------------------------------------
// KV projection, split-K(8) + FFMA2 8x8 microkernel.
// z = kv(2) x kseg(8); each CTA: 128x64 tile over K=128. Grid (5, 8, 16).
// 640 CTAs (~17 warps/SM) — latency hidden by cross-CTA interleave.
// ---------------------------------------------------------------------------
__global__ __launch_bounds__(128) void kv_proj_splitk_kernel(
    const float* __restrict__ kv,
    const float* __restrict__ Wk,
    const float* __restrict__ Wv)
{
    const int z = blockIdx.z;
    const bool isK = (z < 8);
    const int ksg = z & 7;
    const float* __restrict__ W = isK ? Wk : Wv;
    float* __restrict__ Cout = g_KVpart[z];

    __shared__ float As[16][128];
    __shared__ float Bs[16][64];

    const int tid  = threadIdx.x;
    const int warp = tid >> 5;
    const int lane = tid & 31;
    const int wm = warp & 1;
    const int wn = warp >> 1;
    const int lm = lane & 7;
    const int ln = lane >> 3;
    const int mFrag = wm * 64 + lm * 4;     // and +32
    const int nFrag = wn * 32 + ln * 4;     // and +16

    const int mBase = blockIdx.x * 128;
    const int nBase = blockIdx.y * 64;

    ull acc[8][4];
    #pragma unroll
    for (int i = 0; i < 8; ++i)
        #pragma unroll
        for (int jp = 0; jp < 4; ++jp) acc[i][jp] = 0ull;

    const int gm = mBase + tid;            // A row for staging
    const bool mOK = gm < MKV_;
    const int bkc = tid >> 4, bf4 = (tid & 15) * 4;

    const int kLo = ksg * 128;
    float4 aR[4], bR[2];

    // prologue (chunk 0)
    #pragma unroll
    for (int r = 0; r < 4; ++r)
        aR[r] = mOK ? *(const float4*)(kv + (size_t)gm * DKV_ + kLo + 4 * r)
                    : make_float4(0.f, 0.f, 0.f, 0.f);
    #pragma unroll
    for (int r = 0; r < 2; ++r)
        bR[r] = *(const float4*)(W + (size_t)(kLo + bkc + 8 * r) * INNER_ + nBase + bf4);

    for (int t = 0; t < 8; ++t) {
        // store current chunk (A transposed; banks = tid%32, conflict-free)
        #pragma unroll
        for (int r = 0; r < 4; ++r) {
            As[4 * r + 0][tid] = aR[r].x;
            As[4 * r + 1][tid] = aR[r].y;
            As[4 * r + 2][tid] = aR[r].z;
            As[4 * r + 3][tid] = aR[r].w;
        }
        #pragma unroll
        for (int r = 0; r < 2; ++r)
            *(float4*)&Bs[bkc + 8 * r][bf4] = bR[r];
        __syncthreads();

        if (t + 1 < 8) {
            const int k0 = kLo + (t + 1) * 16;
            #pragma unroll
            for (int r = 0; r < 4; ++r)
                aR[r] = mOK ? *(const float4*)(kv + (size_t)gm * DKV_ + k0 + 4 * r)
                            : make_float4(0.f, 0.f, 0.f, 0.f);
            #pragma unroll
            for (int r = 0; r < 2; ++r)
                bR[r] = *(const float4*)(W + (size_t)(k0 + bkc + 8 * r) * INNER_ + nBase + bf4);
        }

        #pragma unroll
        for (int kk = 0; kk < 16; ++kk) {
            const float4 a0 = *(const float4*)&As[kk][mFrag];
            const float4 a1 = *(const float4*)&As[kk][mFrag + 32];
            const ulonglong2 b0 = *(const ulonglong2*)&Bs[kk][nFrag];
            const ulonglong2 b1 = *(const ulonglong2*)&Bs[kk][nFrag + 16];
            const ull bp[4] = { b0.x, b0.y, b1.x, b1.y };
            ull ad[8];
            ad[0] = pack2(a0.x, a0.x); ad[1] = pack2(a0.y, a0.y);
            ad[2] = pack2(a0.z, a0.z); ad[3] = pack2(a0.w, a0.w);
            ad[4] = pack2(a1.x, a1.x); ad[5] = pack2(a1.y, a1.y);
            ad[6] = pack2(a1.z, a1.z); ad[7] = pack2(a1.w, a1.w);
            #pragma unroll
            for (int i = 0; i < 8; ++i)
                #pragma unroll
                for (int jp = 0; jp < 4; ++jp)
                    ffma2(acc[i][jp], ad[i], bp[jp]);
        }
        __syncthreads();
    }

    // epilogue: Cout[m][INNER] row-major, float2 per n-pair, m guarded
    #pragma unroll
    for (int i = 0; i < 8; ++i) {
        const int m = mBase + mFrag + ((i < 4) ? i : (i + 28));  // +32 offset half
        if (m < MKV_) {
            float* row = Cout + (size_t)m * INNER_ + nBase + nFrag;
            #pragma unroll
            for (int jp = 0; jp < 4; ++jp) {
                const int off = ((jp & 1) * 2) + ((jp >> 1) * 16);
                const float2 v = unpack2(acc[i][jp]);
                *(float2*)(row + off) = v;
            }
        }
    }
}

// Reduce the 8 split-K partials; apply K scale (0.125). 2464 blocks x 256.
__global__ __launch_bounds__(256) void kv_reduce_kernel()
{
    const size_t PER = (size_t)MKV_ * INNER_;          // 315392
    const size_t idx = (size_t)blockIdx.x * 256 + threadIdx.x;  // < 2*PER
    const int kvsel = (int)(idx / PER);
    const size_t e = idx - (size_t)kvsel * PER;
    const int zb = kvsel * 8;
    float s = 0.f;
    #pragma unroll
    for (int j = 0; j < 8; ++j) s += g_KVpart[zb + j][e];
    if (kvsel == 0) g_Kp[e] = s * 0.125f;
    else            g_Vp[e] = s;
}

// ---------------------------------------------------------------------------
// mma.sync bf16 2-split GEMM (D += Ahi*Bhi + Ahi*Blo + Alo*Bhi):
//   MODE 0: A = g_Aq* [b][4096][320], B = g_Bq* [512][320], C = g_QpT
//   MODE 1: A = g_O*  [b][4096][512], B = g_Bo* [320][512], C = out + bias
// Block tile M=128, N=64; 4 warps (2x2); warp 64x32 = 4x4 m16n8 tiles.
// K-chunk 32. smem rows: 64B + 16B pad -> 80B stride. cp.async double buffer.
// ---------------------------------------------------------------------------
#define ROWB      80
#define OFF_AHI   0
#define OFF_ALO   (128 * ROWB)                      // 10240
#define OFF_BHI   (2 * 128 * ROWB)                  // 20480
#define OFF_BLO   (2 * 128 * ROWB + 64 * ROWB)      // 25600
#define BUF_BYTES (2 * 128 * ROWB + 2 * 64 * ROWB)  // 30720
#define MMA_SMEM_TOTAL (2 * BUF_BYTES)              // 61440

template <int MODE>
__global__ __launch_bounds__(128) void gemm_mma_kernel(
    const float* __restrict__ bias, float* __restrict__ Carg)
{
    constexpr int K    = (MODE == 0) ? C_     : INNER_;
    constexpr int Nout = (MODE == 0) ? INNER_ : C_;
    constexpr int NT   = K / 32;

    extern __shared__ char dsm[];
    const uint32_t sb = smem_u32(dsm);

    const int b = blockIdx.z;
    const int mBase = blockIdx.x * 128;
    const int nBase = blockIdx.y * 64;
    const int tid  = threadIdx.x;
    const int warp = tid >> 5;
    const int lane = tid & 31;
    const int wm = warp & 1;      // m half 0/64
    const int wn = warp >> 1;     // n half 0/32

    const char* Ahi_g = (const char*)((MODE == 0) ? g_Aqhi : g_Ohi) +
                        ((size_t)b * N_ + mBase) * K * 2;
    const char* Alo_g = (const char*)((MODE == 0) ? g_Aqlo : g_Olo) +
                        ((size_t)b * N_ + mBase) * K * 2;
    const char* Bhi_g = (const char*)((MODE == 0) ? g_Bqhi : g_Bohi) +
                        (size_t)nBase * K * 2;
    const char* Blo_g = (const char*)((MODE == 0) ? g_Bqlo : g_Bolo) +
                        (size_t)nBase * K * 2;

    float acc[4][4][4] = {};

    const int arow = tid >> 2, ac = (tid & 3) * 16;
    const uint32_t aoff = (uint32_t)((wm * 64 + (lane & 7) + ((lane >> 3) & 1) * 8) * ROWB
                                     + ((lane >> 4) & 1) * 16);
    const uint32_t boff = (uint32_t)((wn * 32 + (lane & 7)) * ROWB
                                     + ((lane >> 3) & 1) * 16);

    // prologue: stage chunk 0 -> buffer 0
    {
        #pragma unroll
        for (int i = 0; i < 4; ++i) {
            const int r = arow + 32 * i;
            const uint32_t s = sb + (uint32_t)(r * ROWB + ac);
            cp_async16(s + OFF_AHI, Ahi_g + (size_t)r * K * 2 + ac);
            cp_async16(s + OFF_ALO, Alo_g + (size_t)r * K * 2 + ac);
        }
        #pragma unroll
        for (int i = 0; i < 2; ++i) {
            const int r = arow + 32 * i;
            const uint32_t s = sb + (uint32_t)(r * ROWB + ac);
            cp_async16(s + OFF_BHI, Bhi_g + (size_t)r * K * 2 + ac);
            cp_async16(s + OFF_BLO, Blo_g + (size_t)r * K * 2 + ac);
        }
        cp_async_commit();
    }

    for (int t = 0; t < NT; ++t) {
        cp_async_wait_all();
        __syncthreads();

        if (t + 1 < NT) {
            const uint32_t bs = sb + ((t + 1) & 1) * BUF_BYTES;
            const int kB = (t + 1) * 64;
            #pragma unroll
            for (int i = 0; i < 4; ++i) {
                const int r = arow + 32 * i;
                const uint32_t s = bs + (uint32_t)(r * ROWB + ac);
                cp_async16(s + OFF_AHI, Ahi_g + (size_t)r * K * 2 + kB + ac);
                cp_async16(s + OFF_ALO, Alo_g + (size_t)r * K * 2 + kB + ac);
            }
            #pragma unroll
            for (int i = 0; i < 2; ++i) {
                const int r = arow + 32 * i;
                const uint32_t s = bs + (uint32_t)(r * ROWB + ac);
                cp_async16(s + OFF_BHI, Bhi_g + (size_t)r * K * 2 + kB + ac);
                cp_async16(s + OFF_BLO, Blo_g + (size_t)r * K * 2 + kB + ac);
            }
            cp_async_commit();
        }

        const uint32_t cb = sb + (t & 1) * BUF_BYTES;
        #pragma unroll
        for (int ks = 0; ks < 2; ++ks) {
            uint32_t bH[4][2], bL[4][2];
            #pragma unroll
            for (int nt = 0; nt < 4; ++nt) {
                const uint32_t ba = cb + boff + (uint32_t)(nt * 8 * ROWB + ks * 32);
                ldm_x2(bH[nt], ba + OFF_BHI);
                ldm_x2(bL[nt], ba + OFF_BLO);
            }
            #pragma unroll
            for (int mt = 0; mt < 4; ++mt) {
                uint32_t aH[4], aL[4];
                const uint32_t aa = cb + aoff + (uint32_t)(mt * 16 * ROWB + ks * 32);
                ldm_x4(aH, aa + OFF_AHI);
                ldm_x4(aL, aa + OFF_ALO);
                #pragma unroll
                for (int nt = 0; nt < 4; ++nt) {
                    mma_bf16(acc[mt][nt], aH, bH[nt]);
                    mma_bf16(acc[mt][nt], aH, bL[nt]);
                    mma_bf16(acc[mt][nt], aL, bH[nt]);
                }
            }
        }
        __syncthreads();
    }

    // epilogue: C[n][m] (+bias)
    float* __restrict__ Cp =
        ((MODE == 0) ? (float*)g_QpT : Carg) + (size_t)b * Nout * N_;
    const int mW = mBase + wm * 64 + (lane >> 2);
    const int nW = nBase + wn * 32 + (lane & 3) * 2;
    #pragma unroll
    for (int mt = 0; mt < 4; ++mt) {
        const int m0 = mW + mt * 16;
        #pragma unroll
        for (int nt = 0; nt < 4; ++nt) {
            const int nn = nW + nt * 8;
            const float b0 = (MODE == 1) ? bias[nn] : 0.f;
            const float b1 = (MODE == 1) ? bias[nn + 1] : 0.f;
            float* p0 = Cp + (size_t)nn * N_;
            float* p1 = Cp + (size_t)(nn + 1) * N_;
            p0[m0]     = acc[mt][nt][0] + b0;
            p1[m0]     = acc[mt][nt][1] + b1;
            p0[m0 + 8] = acc[mt][nt][2] + b0;
            p1[m0 + 8] = acc[mt][nt][3] + b1;
        }
    }
}

// ---------------------------------------------------------------------------
// Attention (fused online softmax), O written as bf16 hi/lo [b][n][inner]
// ---------------------------------------------------------------------------
#define ATTN_SMEM_BYTES (2 * SKV_ * DH_ * (int)sizeof(float))  // 39424

template <int CNT>
__device__ __forceinline__ void attn_chunk(
    const float* __restrict__ Ks, const float* __restrict__ Vs, int s0,
    const ull* __restrict__ q2, ull* __restrict__ acc2, float& m, float& sum)
{
    float l[CNT];
    #pragma unroll
    for (int j = 0; j < CNT; ++j) {
        const int s = s0 + j;
        ull da = 0ull, db = 0ull;
        #pragma unroll
        for (int jj = 0; jj < 16; jj += 2) {
            const ulonglong2 k0 = *(const ulonglong2*)(Ks + s * DH_ + jj * 4);
            const ulonglong2 k1 = *(const ulonglong2*)(Ks + s * DH_ + jj * 4 + 4);
            ffma2(da, q2[2 * jj],     k0.x);
            ffma2(da, q2[2 * jj + 1], k0.y);
            ffma2(db, q2[2 * jj + 2], k1.x);
            ffma2(db, q2[2 * jj + 3], k1.y);
        }
        const float2 pa = unpack2(da), pb = unpack2(db);
        l[j] = (pa.x + pa.y) + (pb.x + pb.y);
    }
    float cmax = l[0];
    #pragma unroll
    for (int j = 1; j < CNT; ++j) cmax = fmaxf(cmax, l[j]);
    const float mn = fmaxf(m, cmax);
    const float corr = __expf(m - mn);
    m = mn;
    sum *= corr;
    const ull c2 = pack2(corr, corr);
    #pragma unroll
    for (int p = 0; p < 32; ++p) mul2(acc2[p], c2);
    #pragma unroll
    for (int j = 0; j < CNT; ++j) { l[j] = __expf(l[j] - mn); sum += l[j]; }
    #pragma unroll
    for (int j = 0; j < CNT; ++j) {
        const int s = s0 + j;
        const ull p2 = pack2(l[j], l[j]);
        #pragma unroll
        for (int jj = 0; jj < 16; ++jj) {
            const ulonglong2 v2 = *(const ulonglong2*)(Vs + s * DH_ + jj * 4);
            ffma2(acc2[2 * jj],     p2, v2.x);
            ffma2(acc2[2 * jj + 1], p2, v2.y);
        }
    }
}

__global__ __launch_bounds__(128, 3) void attn_kernel()
{
    extern __shared__ float sm[];
    float* __restrict__ Ks = sm;
    float* __restrict__ Vs = sm + SKV_ * DH_;

    const int b = blockIdx.z;
    const int h = blockIdx.y;
    const int tid = threadIdx.x;
    const int n = blockIdx.x * 128 + tid;

    {
        const float* __restrict__ kp = g_Kp + (size_t)b * SKV_ * INNER_ + h * DH_;
        const float* __restrict__ vp = g_Vp + (size_t)b * SKV_ * INNER_ + h * DH_;
        for (int i4 = tid; i4 < SKV_ * DH_ / 4; i4 += 128) {
            const int s = i4 >> 4, d4 = (i4 & 15) << 2;
            *(float4*)(Ks + (i4 << 2)) = *(const float4*)(kp + (size_t)s * INNER_ + d4);
            *(float4*)(Vs + (i4 << 2)) = *(const float4*)(vp + (size_t)s * INNER_ + d4);
        }
    }

    ull q2[DH_ / 2];
    {
        const float* __restrict__ qp =
            g_QpT + (size_t)b * INNER_ * N_ + (size_t)h * DH_ * N_ + n;
        #pragma unroll
        for (int p = 0; p < DH_ / 2; ++p)
            q2[p] = pack2(qp[(size_t)(2 * p) * N_], qp[(size_t)(2 * p + 1) * N_]);
    }
    __syncthreads();

    ull acc2[DH_ / 2];
    #pragma unroll
    for (int p = 0; p < DH_ / 2; ++p) acc2[p] = 0ull;
    float m = -1e30f, sum = 0.f;

    for (int c = 0; c < 9; ++c)
        attn_chunk<8>(Ks, Vs, c * 8, q2, acc2, m, sum);
    attn_chunk<5>(Ks, Vs, 72, q2, acc2, m, sum);

    const float inv = 1.f / sum;

    alignas(16) __nv_bfloat16 hib[DH_], lob[DH_];
    #pragma unroll
    for (int p = 0; p < DH_ / 2; ++p) {
        const float2 v = unpack2(acc2[p]);
        bfsplit(v.x * inv, hib[2 * p], lob[2 * p]);
        bfsplit(v.y * inv, hib[2 * p + 1], lob[2 * p + 1]);
    }
    const size_t off = ((size_t)b * N_ + n) * INNER_ + h * DH_;
    char* hp = (char*)g_Ohi + off * 2;
    char* lp = (char*)g_Olo + off * 2;
    #pragma unroll
    for (int i = 0; i < 8; ++i) {
        *(uint4*)(hp + 16 * i) = ((const uint4*)hib)[i];
        *(uint4*)(lp + 16 * i) = ((const uint4*)lob)[i];
    }
}

// ---------------------------------------------------------------------------
extern "C" void kernel_launch(void* const* d_in, const int* in_sizes, int n_in,
                              void* d_out, int out_size)
{
    const float* query = (const float*)d_in[0];  // [B,C,H,W]
    const float* kv    = (const float*)d_in[1];  // [B,S,DKV]
    const float* Wq    = (const float*)d_in[2];  // [C,INNER]
    const float* Wk    = (const float*)d_in[3];  // [DKV,INNER]
    const float* Wv    = (const float*)d_in[4];  // [DKV,INNER]
    const float* Wo    = (const float*)d_in[5];  // [INNER,C]
    const float* bo    = (const float*)d_in[6];  // [C]
    float* out = (float*)d_out;

    cudaFuncSetAttribute(gemm_mma_kernel<0>,
                         cudaFuncAttributeMaxDynamicSharedMemorySize, MMA_SMEM_TOTAL);
    cudaFuncSetAttribute(gemm_mma_kernel<1>,
                         cudaFuncAttributeMaxDynamicSharedMemorySize, MMA_SMEM_TOTAL);

    {   // prepass: transpose+split query and weights (dst selected in-kernel)
        dim3 blk(32, 8);
        split_query_kernel<<<dim3(N_ / 32, C_ / 32, B_), blk>>>(query);
        split_w_kernel<0><<<dim3(INNER_ / 32, C_ / 32, 1), blk>>>(Wq);
        split_w_kernel<1><<<dim3(C_ / 32, INNER_ / 32, 1), blk>>>(Wo);
    }
    {   // K & V projections: split-K(8) FFMA2 partials then reduce
        dim3 grid(5, INNER_ / 64, 16);   // 5 x 8 x 16 = 640 CTAs (M padded to 640)
        kv_proj_splitk_kernel<<<grid, 128>>>(kv, Wk, Wv);
        kv_reduce_kernel<<<(2 * MKV_ * INNER_) / 256, 256>>>();
    }
    {   // Q projection (mma.sync bf16 split) -> g_QpT
        dim3 grid(N_ / 128, INNER_ / 64, B_);          // 32 x 8 x 8
        gemm_mma_kernel<0><<<grid, 128, MMA_SMEM_TOTAL>>>(nullptr, nullptr);
    }
    {   // attention (fused online softmax) -> g_Ohi/g_Olo
        dim3 grid(N_ / 128, HEADS_, B_);
        attn_kernel<<<grid, 128, ATTN_SMEM_BYTES>>>();
    }
    {   // output projection (mma.sync bf16 split) -> out (NCHW) + bias
        dim3 grid(N_ / 128, C_ / 64, B_);              // 32 x 5 x 8
        gemm_mma_kernel<1><<<grid, 128, MMA_SMEM_TOTAL>>>(bo, out);
    }
}

// round 17
// speedup vs baseline: 1.5418x; 1.0700x over previous
#include <cuda_runtime.h>
#include <cuda_bf16.h>
#include <math.h>
#include <stdint.h>

// Problem constants
#define B_    8
#define C_    320
#define N_    4096     // H*W  (= M of both big GEMMs)
#define SKV_  77
#define DKV_  1024
#define HEADS_ 8
#define DH_   64
#define INNER_ 512
#define MKV_  (B_ * SKV_)   // 616

typedef unsigned long long ull;

// ---- packed fp32x2 helpers ----
__device__ __forceinline__ void ffma2(ull& d, ull a, ull b) {
    asm("fma.rn.f32x2 %0, %1, %2, %0;" : "+l"(d) : "l"(a), "l"(b));
}
__device__ __forceinline__ void mul2(ull& d, ull a) {
    asm("mul.rn.f32x2 %0, %0, %1;" : "+l"(d) : "l"(a));
}
__device__ __forceinline__ ull pack2(float x, float y) {
    ull r; asm("mov.b64 %0, {%1, %2};" : "=l"(r) : "f"(x), "f"(y)); return r;
}
__device__ __forceinline__ float2 unpack2(ull v) {
    float2 r; asm("mov.b64 {%0, %1}, %2;" : "=f"(r.x), "=f"(r.y) : "l"(v)); return r;
}

// ---- portable tensor-core primitives (sm_80+; legal on compute_103) ----
__device__ __forceinline__ uint32_t smem_u32(const void* p) {
    uint32_t a;
    asm("{ .reg .u64 t; cvta.to.shared.u64 t, %1; cvt.u32.u64 %0, t; }"
        : "=r"(a) : "l"(p));
    return a;
}
__device__ __forceinline__ void ldm_x4(uint32_t* r, uint32_t addr) {
    asm volatile("ldmatrix.sync.aligned.m8n8.x4.shared.b16 {%0,%1,%2,%3}, [%4];"
        : "=r"(r[0]), "=r"(r[1]), "=r"(r[2]), "=r"(r[3]) : "r"(addr));
}
__device__ __forceinline__ void ldm_x2(uint32_t* r, uint32_t addr) {
    asm volatile("ldmatrix.sync.aligned.m8n8.x2.shared.b16 {%0,%1}, [%2];"
        : "=r"(r[0]), "=r"(r[1]) : "r"(addr));
}
__device__ __forceinline__ void mma_bf16(float* d, const uint32_t* a, const uint32_t* b) {
    asm volatile("mma.sync.aligned.m16n8k16.row.col.f32.bf16.bf16.f32 "
        "{%0,%1,%2,%3}, {%4,%5,%6,%7}, {%8,%9}, {%0,%1,%2,%3};"
        : "+f"(d[0]), "+f"(d[1]), "+f"(d[2]), "+f"(d[3])
        : "r"(a[0]), "r"(a[1]), "r"(a[2]), "r"(a[3]), "r"(b[0]), "r"(b[1]));
}
__device__ __forceinline__ void cp_async16(uint32_t smem_addr, const void* gptr) {
    asm volatile("cp.async.ca.shared.global [%0], [%1], 16;\n"
                 :: "r"(smem_addr), "l"(gptr));
}
__device__ __forceinline__ void cp_async_commit() {
    asm volatile("cp.async.commit_group;\n");
}
__device__ __forceinline__ void cp_async_wait_all() {
    asm volatile("cp.async.wait_group 0;\n");
}

// Scratch (__device__ globals; referenced ONLY in device code — R5/R12 lesson)
__device__ float g_QpT[(size_t)B_ * INNER_ * N_];   // [b][inner][n] fp32
__device__ float g_Kp [(size_t)B_ * SKV_ * INNER_]; // pre-scaled
__device__ float g_Vp [(size_t)B_ * SKV_ * INNER_];
__device__ float g_KVpart[16][(size_t)MKV_ * INNER_]; // split-K partials (z = kv*8+ks)
__device__ __align__(128) __nv_bfloat16 g_Aqhi[(size_t)B_ * N_ * C_];     // query^T split [b][n][c]
__device__ __align__(128) __nv_bfloat16 g_Aqlo[(size_t)B_ * N_ * C_];
__device__ __align__(128) __nv_bfloat16 g_Ohi [(size_t)B_ * N_ * INNER_]; // attn out split [b][n][inner]
__device__ __align__(128) __nv_bfloat16 g_Olo [(size_t)B_ * N_ * INNER_];
__device__ __align__(128) __nv_bfloat16 g_Bqhi[(size_t)INNER_ * C_];      // Wq^T split [n][k]
__device__ __align__(128) __nv_bfloat16 g_Bqlo[(size_t)INNER_ * C_];
__device__ __align__(128) __nv_bfloat16 g_Bohi[(size_t)C_ * INNER_];      // Wo^T split [n][k]
__device__ __align__(128) __nv_bfloat16 g_Bolo[(size_t)C_ * INNER_];

__device__ __forceinline__ void bfsplit(float x, __nv_bfloat16& h, __nv_bfloat16& l) {
    h = __float2bfloat16(x);
    l = __float2bfloat16(x - __bfloat162float(h));
}

// ---------------------------------------------------------------------------
// Prepass: transpose+split query [C][N] -> [n][c] bf16 hi/lo
// ---------------------------------------------------------------------------
__global__ __launch_bounds__(256) void split_query_kernel(const float* __restrict__ q)
{
    __shared__ float t[32][33];
    const int b = blockIdx.z, nB = blockIdx.x * 32, cB = blockIdx.y * 32;
    const int tx = threadIdx.x, ty = threadIdx.y;
    const float* src = q + (size_t)b * C_ * N_;
    #pragma unroll
    for (int i = 0; i < 4; ++i)
        t[ty + 8 * i][tx] = src[(size_t)(cB + ty + 8 * i) * N_ + nB + tx];
    __syncthreads();
    #pragma unroll
    for (int i = 0; i < 4; ++i) {
        const float x = t[tx][ty + 8 * i];
        __nv_bfloat16 h, l; bfsplit(x, h, l);
        const size_t o = ((size_t)b * N_ + nB + ty + 8 * i) * C_ + cB + tx;
        g_Aqhi[o] = h; g_Aqlo[o] = l;
    }
}

// Prepass: transpose+split weight -> [n][k] bf16 hi/lo (dst selected in-kernel).
template <int WSEL>
__global__ __launch_bounds__(256) void split_w_kernel(const float* __restrict__ src)
{
    constexpr int K    = (WSEL == 0) ? C_     : INNER_;
    constexpr int Nout = (WSEL == 0) ? INNER_ : C_;
    __nv_bfloat16* __restrict__ dhi = (WSEL == 0) ? g_Bqhi : g_Bohi;
    __nv_bfloat16* __restrict__ dlo = (WSEL == 0) ? g_Bqlo : g_Bolo;

    __shared__ float t[32][33];
    const int nB = blockIdx.x * 32, kB = blockIdx.y * 32;
    const int tx = threadIdx.x, ty = threadIdx.y;
    #pragma unroll
    for (int i = 0; i < 4; ++i)
        t[ty + 8 * i][tx] = src[(size_t)(kB + ty + 8 * i) * Nout + nB + tx];
    __syncthreads();
    #pragma unroll
    for (int i = 0; i < 4; ++i) {
        const float x = t[tx][ty + 8 * i];
        __nv_bfloat16 h, l; bfsplit(x, h, l);
        const size_t o = (size_t)(nB + ty + 8 * i) * K + kB + tx;
        dhi[o] = h; dlo[o] = l;
    }
}

// ---------------------------------------------------------------------------
// KV projection, split-K(8) + FFMA2 8x8 microkernel (unchanged from R16).
// ---------------------------------------------------------------------------
__global__ __launch_bounds__(128) void kv_proj_splitk_kernel(
    const float* __restrict__ kv,
    const float* __restrict__ Wk,
    const float* __restrict__ Wv)
{
    const int z = blockIdx.z;
    const bool isK = (z < 8);
    const int ksg = z & 7;
    const float* __restrict__ W = isK ? Wk : Wv;
    float* __restrict__ Cout = g_KVpart[z];

    __shared__ float As[16][128];
    __shared__ float Bs[16][64];

    const int tid  = threadIdx.x;
    const int warp = tid >> 5;
    const int lane = tid & 31;
    const int wm = warp & 1;
    const int wn = warp >> 1;
    const int lm = lane & 7;
    const int ln = lane >> 3;
    const int mFrag = wm * 64 + lm * 4;
    const int nFrag = wn * 32 + ln * 4;

    const int mBase = blockIdx.x * 128;
    const int nBase = blockIdx.y * 64;

    ull acc[8][4];
    #pragma unroll
    for (int i = 0; i < 8; ++i)
        #pragma unroll
        for (int jp = 0; jp < 4; ++jp) acc[i][jp] = 0ull;

    const int gm = mBase + tid;
    const bool mOK = gm < MKV_;
    const int bkc = tid >> 4, bf4 = (tid & 15) * 4;

    const int kLo = ksg * 128;
    float4 aR[4], bR[2];

    #pragma unroll
    for (int r = 0; r < 4; ++r)
        aR[r] = mOK ? *(const float4*)(kv + (size_t)gm * DKV_ + kLo + 4 * r)
                    : make_float4(0.f, 0.f, 0.f, 0.f);
    #pragma unroll
    for (int r = 0; r < 2; ++r)
        bR[r] = *(const float4*)(W + (size_t)(kLo + bkc + 8 * r) * INNER_ + nBase + bf4);

    for (int t = 0; t < 8; ++t) {
        #pragma unroll
        for (int r = 0; r < 4; ++r) {
            As[4 * r + 0][tid] = aR[r].x;
            As[4 * r + 1][tid] = aR[r].y;
            As[4 * r + 2][tid] = aR[r].z;
            As[4 * r + 3][tid] = aR[r].w;
        }
        #pragma unroll
        for (int r = 0; r < 2; ++r)
            *(float4*)&Bs[bkc + 8 * r][bf4] = bR[r];
        __syncthreads();

        if (t + 1 < 8) {
            const int k0 = kLo + (t + 1) * 16;
            #pragma unroll
            for (int r = 0; r < 4; ++r)
                aR[r] = mOK ? *(const float4*)(kv + (size_t)gm * DKV_ + k0 + 4 * r)
                            : make_float4(0.f, 0.f, 0.f, 0.f);
            #pragma unroll
            for (int r = 0; r < 2; ++r)
                bR[r] = *(const float4*)(W + (size_t)(k0 + bkc + 8 * r) * INNER_ + nBase + bf4);
        }

        #pragma unroll
        for (int kk = 0; kk < 16; ++kk) {
            const float4 a0 = *(const float4*)&As[kk][mFrag];
            const float4 a1 = *(const float4*)&As[kk][mFrag + 32];
            const ulonglong2 b0 = *(const ulonglong2*)&Bs[kk][nFrag];
            const ulonglong2 b1 = *(const ulonglong2*)&Bs[kk][nFrag + 16];
            const ull bp[4] = { b0.x, b0.y, b1.x, b1.y };
            ull ad[8];
            ad[0] = pack2(a0.x, a0.x); ad[1] = pack2(a0.y, a0.y);
            ad[2] = pack2(a0.z, a0.z); ad[3] = pack2(a0.w, a0.w);
            ad[4] = pack2(a1.x, a1.x); ad[5] = pack2(a1.y, a1.y);
            ad[6] = pack2(a1.z, a1.z); ad[7] = pack2(a1.w, a1.w);
            #pragma unroll
            for (int i = 0; i < 8; ++i)
                #pragma unroll
                for (int jp = 0; jp < 4; ++jp)
                    ffma2(acc[i][jp], ad[i], bp[jp]);
        }
        __syncthreads();
    }

    #pragma unroll
    for (int i = 0; i < 8; ++i) {
        const int m = mBase + mFrag + ((i < 4) ? i : (i + 28));
        if (m < MKV_) {
            float* row = Cout + (size_t)m * INNER_ + nBase + nFrag;
            #pragma unroll
            for (int jp = 0; jp < 4; ++jp) {
                const int off = ((jp & 1) * 2) + ((jp >> 1) * 16);
                const float2 v = unpack2(acc[i][jp]);
                *(float2*)(row + off) = v;
            }
        }
    }
}

// Reduce the 8 split-K partials; apply K scale (0.125). 2464 blocks x 256.
__global__ __launch_bounds__(256) void kv_reduce_kernel()
{
    const size_t PER = (size_t)MKV_ * INNER_;
    const size_t idx = (size_t)blockIdx.x * 256 + threadIdx.x;
    const int kvsel = (int)(idx / PER);
    const size_t e = idx - (size_t)kvsel * PER;
    const int zb = kvsel * 8;
    float s = 0.f;
    #pragma unroll
    for (int j = 0; j < 8; ++j) s += g_KVpart[zb + j][e];
    if (kvsel == 0) g_Kp[e] = s * 0.125f;
    else            g_Vp[e] = s;
}

// ---------------------------------------------------------------------------
// mma.sync bf16 2-split GEMM (unchanged from R16 — measured at HMMA roofline)
// ---------------------------------------------------------------------------
#define ROWB      80
#define OFF_AHI   0
#define OFF_ALO   (128 * ROWB)
#define OFF_BHI   (2 * 128 * ROWB)
#define OFF_BLO   (2 * 128 * ROWB + 64 * ROWB)
#define BUF_BYTES (2 * 128 * ROWB + 2 * 64 * ROWB)
#define MMA_SMEM_TOTAL (2 * BUF_BYTES)

template <int MODE>
__global__ __launch_bounds__(128) void gemm_mma_kernel(
    const float* __restrict__ bias, float* __restrict__ Carg)
{
    constexpr int K    = (MODE == 0) ? C_     : INNER_;
    constexpr int Nout = (MODE == 0) ? INNER_ : C_;
    constexpr int NT   = K / 32;

    extern __shared__ char dsm[];
    const uint32_t sb = smem_u32(dsm);

    const int b = blockIdx.z;
    const int mBase = blockIdx.x * 128;
    const int nBase = blockIdx.y * 64;
    const int tid  = threadIdx.x;
    const int warp = tid >> 5;
    const int lane = tid & 31;
    const int wm = warp & 1;
    const int wn = warp >> 1;

    const char* Ahi_g = (const char*)((MODE == 0) ? g_Aqhi : g_Ohi) +
                        ((size_t)b * N_ + mBase) * K * 2;
    const char* Alo_g = (const char*)((MODE == 0) ? g_Aqlo : g_Olo) +
                        ((size_t)b * N_ + mBase) * K * 2;
    const char* Bhi_g = (const char*)((MODE == 0) ? g_Bqhi : g_Bohi) +
                        (size_t)nBase * K * 2;
    const char* Blo_g = (const char*)((MODE == 0) ? g_Bqlo : g_Bolo) +
                        (size_t)nBase * K * 2;

    float acc[4][4][4] = {};

    const int arow = tid >> 2, ac = (tid & 3) * 16;
    const uint32_t aoff = (uint32_t)((wm * 64 + (lane & 7) + ((lane >> 3) & 1) * 8) * ROWB
                                     + ((lane >> 4) & 1) * 16);
    const uint32_t boff = (uint32_t)((wn * 32 + (lane & 7)) * ROWB
                                     + ((lane >> 3) & 1) * 16);

    {
        #pragma unroll
        for (int i = 0; i < 4; ++i) {
            const int r = arow + 32 * i;
            const uint32_t s = sb + (uint32_t)(r * ROWB + ac);
            cp_async16(s + OFF_AHI, Ahi_g + (size_t)r * K * 2 + ac);
            cp_async16(s + OFF_ALO, Alo_g + (size_t)r * K * 2 + ac);
        }
        #pragma unroll
        for (int i = 0; i < 2; ++i) {
            const int r = arow + 32 * i;
            const uint32_t s = sb + (uint32_t)(r * ROWB + ac);
            cp_async16(s + OFF_BHI, Bhi_g + (size_t)r * K * 2 + ac);
            cp_async16(s + OFF_BLO, Blo_g + (size_t)r * K * 2 + ac);
        }
        cp_async_commit();
    }

    for (int t = 0; t < NT; ++t) {
        cp_async_wait_all();
        __syncthreads();

        if (t + 1 < NT) {
            const uint32_t bs = sb + ((t + 1) & 1) * BUF_BYTES;
            const int kB = (t + 1) * 64;
            #pragma unroll
            for (int i = 0; i < 4; ++i) {
                const int r = arow + 32 * i;
                const uint32_t s = bs + (uint32_t)(r * ROWB + ac);
                cp_async16(s + OFF_AHI, Ahi_g + (size_t)r * K * 2 + kB + ac);
                cp_async16(s + OFF_ALO, Alo_g + (size_t)r * K * 2 + kB + ac);
            }
            #pragma unroll
            for (int i = 0; i < 2; ++i) {
                const int r = arow + 32 * i;
                const uint32_t s = bs + (uint32_t)(r * ROWB + ac);
                cp_async16(s + OFF_BHI, Bhi_g + (size_t)r * K * 2 + kB + ac);
                cp_async16(s + OFF_BLO, Blo_g + (size_t)r * K * 2 + kB + ac);
            }
            cp_async_commit();
        }

        const uint32_t cb = sb + (t & 1) * BUF_BYTES;
        #pragma unroll
        for (int ks = 0; ks < 2; ++ks) {
            uint32_t bH[4][2], bL[4][2];
            #pragma unroll
            for (int nt = 0; nt < 4; ++nt) {
                const uint32_t ba = cb + boff + (uint32_t)(nt * 8 * ROWB + ks * 32);
                ldm_x2(bH[nt], ba + OFF_BHI);
                ldm_x2(bL[nt], ba + OFF_BLO);
            }
            #pragma unroll
            for (int mt = 0; mt < 4; ++mt) {
                uint32_t aH[4], aL[4];
                const uint32_t aa = cb + aoff + (uint32_t)(mt * 16 * ROWB + ks * 32);
                ldm_x4(aH, aa + OFF_AHI);
                ldm_x4(aL, aa + OFF_ALO);
                #pragma unroll
                for (int nt = 0; nt < 4; ++nt) {
                    mma_bf16(acc[mt][nt], aH, bH[nt]);
                    mma_bf16(acc[mt][nt], aH, bL[nt]);
                    mma_bf16(acc[mt][nt], aL, bH[nt]);
                }
            }
        }
        __syncthreads();
    }

    float* __restrict__ Cp =
        ((MODE == 0) ? (float*)g_QpT : Carg) + (size_t)b * Nout * N_;
    const int mW = mBase + wm * 64 + (lane >> 2);
    const int nW = nBase + wn * 32 + (lane & 3) * 2;
    #pragma unroll
    for (int mt = 0; mt < 4; ++mt) {
        const int m0 = mW + mt * 16;
        #pragma unroll
        for (int nt = 0; nt < 4; ++nt) {
            const int nn = nW + nt * 8;
            const float b0 = (MODE == 1) ? bias[nn] : 0.f;
            const float b1 = (MODE == 1) ? bias[nn + 1] : 0.f;
            float* p0 = Cp + (size_t)nn * N_;
            float* p1 = Cp + (size_t)(nn + 1) * N_;
            p0[m0]     = acc[mt][nt][0] + b0;
            p1[m0]     = acc[mt][nt][1] + b1;
            p0[m0 + 8] = acc[mt][nt][2] + b0;
            p1[m0 + 8] = acc[mt][nt][3] + b1;
        }
    }
}

// ---------------------------------------------------------------------------
// Attention v2 — split-dim: 2 lanes per query row (lane pair l, l^16).
// 256 threads / CTA, 128 rows; each lane owns 32 of the 64 head dims.
// QK^T partial dot combined via one shfl_xor(16) per s; softmax state
// duplicated across the pair (identical math); AV needs no communication.
// Registers ~halve -> 2 CTAs (16 warps)/SM and chains halve.
// ---------------------------------------------------------------------------
#define ATTN_SMEM_BYTES (2 * SKV_ * DH_ * (int)sizeof(float))  // 39424

template <int CNT>
__device__ __forceinline__ void attn_chunk2(
    const float* __restrict__ Ks, const float* __restrict__ Vs, int s0,
    int dOff, const ull* __restrict__ q2, ull* __restrict__ acc2,
    float& m, float& sum)
{
    float l[CNT];
    #pragma unroll
    for (int j = 0; j < CNT; ++j) {
        const int s = s0 + j;
        ull da = 0ull, db = 0ull;
        const float* kb = Ks + s * DH_ + dOff;   // 32 floats (lane's half)
        #pragma unroll
        for (int jj = 0; jj < 8; ++jj) {
            const ulonglong2 k2 = *(const ulonglong2*)(kb + jj * 4);
            ffma2(da, q2[2 * jj],     k2.x);
            ffma2(db, q2[2 * jj + 1], k2.y);
        }
        const float2 pa = unpack2(da), pb = unpack2(db);
        const float part = (pa.x + pa.y) + (pb.x + pb.y);
        l[j] = part + __shfl_xor_sync(0xffffffffu, part, 16);
    }
    float cmax = l[0];
    #pragma unroll
    for (int j = 1; j < CNT; ++j) cmax = fmaxf(cmax, l[j]);
    const float mn = fmaxf(m, cmax);
    const float corr = __expf(m - mn);
    m = mn;
    sum *= corr;
    const ull c2 = pack2(corr, corr);
    #pragma unroll
    for (int p = 0; p < 16; ++p) mul2(acc2[p], c2);
    #pragma unroll
    for (int j = 0; j < CNT; ++j) { l[j] = __expf(l[j] - mn); sum += l[j]; }
    #pragma unroll
    for (int j = 0; j < CNT; ++j) {
        const int s = s0 + j;
        const ull p2 = pack2(l[j], l[j]);
        const float* vb = Vs + s * DH_ + dOff;
        #pragma unroll
        for (int jj = 0; jj < 8; ++jj) {
            const ulonglong2 v2 = *(const ulonglong2*)(vb + jj * 4);
            ffma2(acc2[2 * jj],     p2, v2.x);
            ffma2(acc2[2 * jj + 1], p2, v2.y);
        }
    }
}

__global__ __launch_bounds__(256, 2) void attn_kernel()
{
    extern __shared__ float sm[];
    float* __restrict__ Ks = sm;
    float* __restrict__ Vs = sm + SKV_ * DH_;

    const int b = blockIdx.z;
    const int h = blockIdx.y;
    const int tid = threadIdx.x;
    const int warp = tid >> 5;
    const int lane = tid & 31;
    const int rowl = lane & 15;          // row within warp's 16
    const int h2 = lane >> 4;            // dim half 0/1
    const int n = blockIdx.x * 128 + warp * 16 + rowl;
    const int dOff = h2 * 32;

    // stage K (pre-scaled) and V together (256 threads)
    {
        const float* __restrict__ kp = g_Kp + (size_t)b * SKV_ * INNER_ + h * DH_;
        const float* __restrict__ vp = g_Vp + (size_t)b * SKV_ * INNER_ + h * DH_;
        for (int i4 = tid; i4 < SKV_ * DH_ / 4; i4 += 256) {
            const int s = i4 >> 4, d4 = (i4 & 15) << 2;
            *(float4*)(Ks + (i4 << 2)) = *(const float4*)(kp + (size_t)s * INNER_ + d4);
            *(float4*)(Vs + (i4 << 2)) = *(const float4*)(vp + (size_t)s * INNER_ + d4);
        }
    }

    // q half-row -> 16 packed pairs (dims dOff..dOff+31)
    ull q2[16];
    {
        const float* __restrict__ qp =
            g_QpT + (size_t)b * INNER_ * N_ + (size_t)(h * DH_ + dOff) * N_ + n;
        #pragma unroll
        for (int p = 0; p < 16; ++p)
            q2[p] = pack2(qp[(size_t)(2 * p) * N_], qp[(size_t)(2 * p + 1) * N_]);
    }
    __syncthreads();

    ull acc2[16];
    #pragma unroll
    for (int p = 0; p < 16; ++p) acc2[p] = 0ull;
    float m = -1e30f, sum = 0.f;

    // 77 = 9*8 + 5
    for (int c = 0; c < 9; ++c)
        attn_chunk2<8>(Ks, Vs, c * 8, dOff, q2, acc2, m, sum);
    attn_chunk2<5>(Ks, Vs, 72, dOff, q2, acc2, m, sum);

    const float inv = 1.f / sum;

    // O (this lane's 32 dims) -> bf16 hi/lo, [b][n][inner]
    alignas(16) __nv_bfloat16 hib[32], lob[32];
    #pragma unroll
    for (int p = 0; p < 16; ++p) {
        const float2 v = unpack2(acc2[p]);
        bfsplit(v.x * inv, hib[2 * p], lob[2 * p]);
        bfsplit(v.y * inv, hib[2 * p + 1], lob[2 * p + 1]);
    }
    const size_t off = ((size_t)b * N_ + n) * INNER_ + h * DH_ + dOff;
    char* hp = (char*)g_Ohi + off * 2;
    char* lp = (char*)g_Olo + off * 2;
    #pragma unroll
    for (int i = 0; i < 4; ++i) {
        *(uint4*)(hp + 16 * i) = ((const uint4*)hib)[i];
        *(uint4*)(lp + 16 * i) = ((const uint4*)lob)[i];
    }
}

// ---------------------------------------------------------------------------
extern "C" void kernel_launch(void* const* d_in, const int* in_sizes, int n_in,
                              void* d_out, int out_size)
{
    const float* query = (const float*)d_in[0];  // [B,C,H,W]
    const float* kv    = (const float*)d_in[1];  // [B,S,DKV]
    const float* Wq    = (const float*)d_in[2];  // [C,INNER]
    const float* Wk    = (const float*)d_in[3];  // [DKV,INNER]
    const float* Wv    = (const float*)d_in[4];  // [DKV,INNER]
    const float* Wo    = (const float*)d_in[5];  // [INNER,C]
    const float* bo    = (const float*)d_in[6];  // [C]
    float* out = (float*)d_out;

    cudaFuncSetAttribute(gemm_mma_kernel<0>,
                         cudaFuncAttributeMaxDynamicSharedMemorySize, MMA_SMEM_TOTAL);
    cudaFuncSetAttribute(gemm_mma_kernel<1>,
                         cudaFuncAttributeMaxDynamicSharedMemorySize, MMA_SMEM_TOTAL);

    {   // prepass: transpose+split query and weights (dst selected in-kernel)
        dim3 blk(32, 8);
        split_query_kernel<<<dim3(N_ / 32, C_ / 32, B_), blk>>>(query);
        split_w_kernel<0><<<dim3(INNER_ / 32, C_ / 32, 1), blk>>>(Wq);
        split_w_kernel<1><<<dim3(C_ / 32, INNER_ / 32, 1), blk>>>(Wo);
    }
    {   // K & V projections: split-K(8) FFMA2 partials then reduce
        dim3 grid(5, INNER_ / 64, 16);
        kv_proj_splitk_kernel<<<grid, 128>>>(kv, Wk, Wv);
        kv_reduce_kernel<<<(2 * MKV_ * INNER_) / 256, 256>>>();
    }
    {   // Q projection (mma.sync bf16 split) -> g_QpT
        dim3 grid(N_ / 128, INNER_ / 64, B_);
        gemm_mma_kernel<0><<<grid, 128, MMA_SMEM_TOTAL>>>(nullptr, nullptr);
    }
    {   // attention v2 (split-dim, fused online softmax) -> g_Ohi/g_Olo
        dim3 grid(N_ / 128, HEADS_, B_);
        attn_kernel<<<grid, 256, ATTN_SMEM_BYTES>>>();
    }
    {   // output projection (mma.sync bf16 split) -> out (NCHW) + bias
        dim3 grid(N_ / 128, C_ / 64, B_);
        gemm_mma_kernel<1><<<grid, 128, MMA_SMEM_TOTAL>>>(bo, out);
    }
}